// round 2
// baseline (speedup 1.0000x reference)
#include <cuda_runtime.h>
#include <math.h>

#define H    2048
#define DIN  784
#define OUTR 9        // num classes (10) - 1

// ---------------- scratch (device globals; no allocation allowed) ----------
__device__ float g_M[H * H];         // scaled W2 (stage2) then scaled W3 (stage3)
__device__ float g_T[H * H];         // stage-3 intermediate (M3 @ W2)
__device__ float g_A[H * DIN];       // A2 then A3
__device__ float g_lf1[H], g_uf1[H], g_w1[H], g_bl1[H], g_bu1[H];
__device__ float g_lf2[H], g_uf2[H], g_w2[H], g_bl2[H], g_bu2[H];
__device__ float g_lf3[H], g_uf3[H], g_w3[H], g_bl3[H], g_bu3[H];
__device__ float g_cl[H], g_cu[H];
__device__ float g_m4a[OUTR * H], g_m4b[OUTR * H];
__device__ float g_bias4[OUTR];

// ---------------- helpers ---------------------------------------------------
__device__ __forceinline__ float spu_f(float x) {
    if (x >= 0.f) return x * x - 0.5f;
    float s = 1.f / (1.f + expf(x));      // sigmoid(-x)
    return s - 1.f;
}
__device__ __forceinline__ float dspu_f(float x) {
    if (x >= 0.f) return 2.f * x;
    float s = 1.f / (1.f + expf(x));
    return -s * (1.f - s);
}

__device__ __forceinline__ void blk_reduce2(float &a, float &b) {
    const unsigned m = 0xffffffffu;
    #pragma unroll
    for (int o = 16; o > 0; o >>= 1) {
        a += __shfl_down_sync(m, a, o);
        b += __shfl_down_sync(m, b, o);
    }
    __shared__ float sa[8], sb[8];
    int w = threadIdx.x >> 5, l = threadIdx.x & 31;
    int nw = blockDim.x >> 5;
    if (l == 0) { sa[w] = a; sb[w] = b; }
    __syncthreads();
    if (w == 0) {
        a = (l < nw) ? sa[l] : 0.f;
        b = (l < nw) ? sb[l] : 0.f;
        #pragma unroll
        for (int o = 4; o > 0; o >>= 1) {
            a += __shfl_down_sync(m, a, o);
            b += __shfl_down_sync(m, b, o);
        }
    }
}

// ---------------- kernels ----------------------------------------------------

// lf[i] = sum_j pos(A[i,j])*lin[j] + neg(A[i,j])*uin[j] + cl[i]
// uf[i] = sum_j pos(A[i,j])*uin[j] + neg(A[i,j])*lin[j] + cu[i]
__global__ void concretize_k(const float* __restrict__ A, int ncols,
                             const float* __restrict__ lin, const float* __restrict__ uin,
                             const float* __restrict__ cl, const float* __restrict__ cu,
                             float* __restrict__ lf, float* __restrict__ uf) {
    int row = blockIdx.x;
    const float* a = A + (size_t)row * ncols;
    float al = 0.f, au = 0.f;
    for (int j = threadIdx.x; j < ncols; j += blockDim.x) {
        float v = a[j], l = lin[j], u = uin[j];
        float p = fmaxf(v, 0.f), n = fminf(v, 0.f);
        al += p * l + n * u;
        au += p * u + n * l;
    }
    blk_reduce2(al, au);
    if (threadIdx.x == 0) { lf[row] = al + cl[row]; uf[row] = au + cu[row]; }
}

__global__ void spu_params_k(const float* __restrict__ lf, const float* __restrict__ uf,
                             const float* __restrict__ pl, const float* __restrict__ pu,
                             float* __restrict__ w, float* __restrict__ bl,
                             float* __restrict__ bu, int n) {
    int i = blockIdx.x * blockDim.x + threadIdx.x;
    if (i >= n) return;
    float l = lf[i], u = uf[i];
    float k1 = dspu_f(l), k2 = dspu_f(u);
    float klo = fminf(k1, k2), khi = fmaxf(k1, k2);
    float wl = fminf(fmaxf(pl[i], klo), khi);
    float wu = fminf(fmaxf(pu[i], klo), khi);
    float p0 = l, p1 = u, p2 = 0.5f * (l + u), p3 = fminf(fmaxf(0.f, l), u);
    float s0 = spu_f(p0), s1 = spu_f(p1), s2 = spu_f(p2), s3 = spu_f(p3);
    float bl_ = fminf(fminf(s0 - wl * p0, s1 - wl * p1), fminf(s2 - wl * p2, s3 - wl * p3));
    float bu_ = fmaxf(fmaxf(s0 - wu * p0, s1 - wu * p1), fmaxf(s2 - wu * p2, s3 - wu * p3));
    w[i] = wl; bl[i] = bl_; bu[i] = bu_;
}

// M[i,j] = W[i,j]*wprev[j]
// cl[i]  = bthis[i] + sum_j pos(W)*blprev + neg(W)*buprev + W*wprev*bprev
// cu[i]  = bthis[i] + sum_j pos(W)*buprev + neg(W)*blprev + W*wprev*bprev
__global__ void scale_bias_k(const float* __restrict__ W, float* __restrict__ M,
                             const float* __restrict__ wprev,
                             const float* __restrict__ blprev, const float* __restrict__ buprev,
                             const float* __restrict__ bthis, const float* __restrict__ bprev,
                             float* __restrict__ cl, float* __restrict__ cu) {
    int row = blockIdx.x;
    const float* wr = W + (size_t)row * H;
    float* mr = M + (size_t)row * H;
    float al = 0.f, au = 0.f;
    for (int j = threadIdx.x; j < H; j += blockDim.x) {
        float v = wr[j];
        float p = fmaxf(v, 0.f), n = fminf(v, 0.f);
        float sb = v * wprev[j] * bprev[j];
        al += p * blprev[j] + n * buprev[j] + sb;
        au += p * buprev[j] + n * blprev[j] + sb;
        mr[j] = v * wprev[j];
    }
    blk_reduce2(al, au);
    if (threadIdx.x == 0) { cl[row] = bthis[row] + al; cu[row] = bthis[row] + au; }
}

// cl[i] += sum_j pos(T)*bl + neg(T)*bu + T*w*b ; cu symmetric
__global__ void bias_T_k(const float* __restrict__ T,
                         const float* __restrict__ w, const float* __restrict__ bl,
                         const float* __restrict__ bu, const float* __restrict__ b,
                         float* __restrict__ cl, float* __restrict__ cu) {
    int row = blockIdx.x;
    const float* tr = T + (size_t)row * H;
    float al = 0.f, au = 0.f;
    for (int j = threadIdx.x; j < H; j += blockDim.x) {
        float v = tr[j];
        float p = fmaxf(v, 0.f), n = fminf(v, 0.f);
        float sb = v * w[j] * b[j];
        al += p * bl[j] + n * bu[j] + sb;
        au += p * bu[j] + n * bl[j] + sb;
    }
    blk_reduce2(al, au);
    if (threadIdx.x == 0) { cl[row] += al; cu[row] += au; }
}

// C[M x N] = (A .* ascale_cols) @ B ; row-major fp32. M,K mult of 128/8; N mult of 4.
__global__ __launch_bounds__(256)
void sgemm_k(int Mdim, int Ndim, int Kdim,
             const float* __restrict__ A, const float* __restrict__ B,
             float* __restrict__ C, const float* __restrict__ ascale) {
    __shared__ float As[8][128];
    __shared__ float Bs[8][128];
    int tid = threadIdx.x;
    int brow = blockIdx.y * 128, bcol = blockIdx.x * 128;
    int tx = tid & 15, ty = tid >> 4;
    float acc[8][8];
    #pragma unroll
    for (int i = 0; i < 8; i++)
        #pragma unroll
        for (int j = 0; j < 8; j++) acc[i][j] = 0.f;

    int arow = tid >> 1, acol = (tid & 1) * 4;
    int bw = tid >> 5, bc = (tid & 31) * 4;

    for (int k0 = 0; k0 < Kdim; k0 += 8) {
        float4 av = *(const float4*)(A + (size_t)(brow + arow) * Kdim + k0 + acol);
        if (ascale) {
            float4 sv = *(const float4*)(ascale + k0 + acol);
            av.x *= sv.x; av.y *= sv.y; av.z *= sv.z; av.w *= sv.w;
        }
        As[acol + 0][arow] = av.x; As[acol + 1][arow] = av.y;
        As[acol + 2][arow] = av.z; As[acol + 3][arow] = av.w;

        int gn = bcol + bc;
        float4 bv;
        if (gn + 3 < Ndim) {
            bv = *(const float4*)(B + (size_t)(k0 + bw) * Ndim + gn);
        } else {
            const float* bp = B + (size_t)(k0 + bw) * Ndim;
            bv.x = (gn + 0 < Ndim) ? bp[gn + 0] : 0.f;
            bv.y = (gn + 1 < Ndim) ? bp[gn + 1] : 0.f;
            bv.z = (gn + 2 < Ndim) ? bp[gn + 2] : 0.f;
            bv.w = (gn + 3 < Ndim) ? bp[gn + 3] : 0.f;
        }
        Bs[bw][bc + 0] = bv.x; Bs[bw][bc + 1] = bv.y;
        Bs[bw][bc + 2] = bv.z; Bs[bw][bc + 3] = bv.w;
        __syncthreads();

        #pragma unroll
        for (int kk = 0; kk < 8; kk++) {
            float ra[8], rb[8];
            #pragma unroll
            for (int i = 0; i < 8; i++) ra[i] = As[kk][ty * 8 + i];
            #pragma unroll
            for (int j = 0; j < 8; j++) rb[j] = Bs[kk][tx * 8 + j];
            #pragma unroll
            for (int i = 0; i < 8; i++)
                #pragma unroll
                for (int j = 0; j < 8; j++)
                    acc[i][j] = fmaf(ra[i], rb[j], acc[i][j]);
        }
        __syncthreads();
    }

    #pragma unroll
    for (int i = 0; i < 8; i++) {
        int gr = brow + ty * 8 + i;
        #pragma unroll
        for (int j = 0; j < 8; j += 4) {
            int gc = bcol + tx * 8 + j;
            if (gc + 3 < Ndim) {
                *(float4*)(C + (size_t)gr * Ndim + gc) =
                    make_float4(acc[i][j], acc[i][j + 1], acc[i][j + 2], acc[i][j + 3]);
            } else {
                for (int d = 0; d < 4; d++)
                    if (gc + d < Ndim) C[(size_t)gr * Ndim + gc + d] = acc[i][j + d];
            }
        }
    }
}

// ---- output stage (9 rows) ----
__global__ void build_m4_k(const float* __restrict__ W4, const float* __restrict__ b4,
                           const int* __restrict__ tl, float* __restrict__ M,
                           float* __restrict__ bias) {
    int t = *tl;
    int idx = blockIdx.x * blockDim.x + threadIdx.x;
    if (idx < OUTR * H) {
        int r = idx / H, j = idx % H;
        int c = (r < t) ? r : r + 1;
        M[idx] = W4[(size_t)c * H + j] - W4[(size_t)t * H + j];
    }
    if (idx < OUTR) {
        int c = (idx < t) ? idx : idx + 1;
        bias[idx] = b4[c] - b4[t];
    }
}

// bias[r] += sum_j pos(A[r,j])*bu[j] + neg(A[r,j])*bl[j] + A[r,j]*w[j]*bnext[j]
__global__ void small_bias_k(const float* __restrict__ A,
                             const float* __restrict__ w, const float* __restrict__ bl,
                             const float* __restrict__ bu, const float* __restrict__ bnext,
                             float* __restrict__ bias) {
    int r = blockIdx.x;
    const float* a = A + (size_t)r * H;
    float au = 0.f, dummy = 0.f;
    for (int j = threadIdx.x; j < H; j += blockDim.x) {
        float v = a[j];
        float p = fmaxf(v, 0.f), n = fminf(v, 0.f);
        au += p * bu[j] + n * bl[j] + v * w[j] * bnext[j];
    }
    blk_reduce2(au, dummy);
    if (threadIdx.x == 0) bias[r] += au;
}

// C[OUTR x N] = (A[OUTR x K] .* ascale_cols) @ B[K x N]
#define SG_CHUNK 512
__global__ void small_gemm_k(int K, int N, const float* __restrict__ A,
                             const float* __restrict__ ascale,
                             const float* __restrict__ B, float* __restrict__ C) {
    __shared__ float sA[OUTR * SG_CHUNK];
    int n = blockIdx.x * blockDim.x + threadIdx.x;
    float acc[OUTR];
    #pragma unroll
    for (int r = 0; r < OUTR; r++) acc[r] = 0.f;
    for (int k0 = 0; k0 < K; k0 += SG_CHUNK) {
        int kc = min(SG_CHUNK, K - k0);
        for (int idx = threadIdx.x; idx < OUTR * kc; idx += blockDim.x) {
            int r = idx / kc, kk = idx % kc;
            sA[r * SG_CHUNK + kk] = A[(size_t)r * K + k0 + kk] * ascale[k0 + kk];
        }
        __syncthreads();
        if (n < N) {
            for (int kk = 0; kk < kc; kk++) {
                float bv = B[(size_t)(k0 + kk) * N + n];
                #pragma unroll
                for (int r = 0; r < OUTR; r++) acc[r] += sA[r * SG_CHUNK + kk] * bv;
            }
        }
        __syncthreads();
    }
    if (n < N)
        #pragma unroll
        for (int r = 0; r < OUTR; r++) C[(size_t)r * N + n] = acc[r];
}

__global__ void final_k(const float* __restrict__ M, const float* __restrict__ lin,
                        const float* __restrict__ uin, const float* __restrict__ bias,
                        float* __restrict__ out) {
    int r = blockIdx.x;
    const float* a = M + (size_t)r * DIN;
    float au = 0.f, dummy = 0.f;
    for (int j = threadIdx.x; j < DIN; j += blockDim.x) {
        float v = a[j];
        au += fmaxf(v, 0.f) * uin[j] + fminf(v, 0.f) * lin[j];
    }
    blk_reduce2(au, dummy);
    if (threadIdx.x == 0) out[r] = au + bias[r];
}

// ---------------- launch -----------------------------------------------------
extern "C" void kernel_launch(void* const* d_in, const int* in_sizes, int n_in,
                              void* d_out, int out_size) {
    const float* W1 = (const float*)d_in[0];
    const float* b1 = (const float*)d_in[1];
    const float* W2 = (const float*)d_in[2];
    const float* b2 = (const float*)d_in[3];
    const float* W3 = (const float*)d_in[4];
    const float* b3 = (const float*)d_in[5];
    const float* W4 = (const float*)d_in[6];
    const float* b4 = (const float*)d_in[7];
    const float* l_in = (const float*)d_in[8];
    const float* u_in = (const float*)d_in[9];
    const float* p_l1 = (const float*)d_in[10];
    const float* p_u1 = (const float*)d_in[11];
    const float* p_l2 = (const float*)d_in[12];
    const float* p_u2 = (const float*)d_in[13];
    const float* p_l3 = (const float*)d_in[14];
    const float* p_u3 = (const float*)d_in[15];
    const int* tl = (const int*)d_in[16];
    float* out = (float*)d_out;

    float *M, *T, *A, *lf1, *uf1, *w1, *bl1, *bu1, *lf2, *uf2, *w2, *bl2, *bu2;
    float *lf3, *uf3, *w3, *bl3, *bu3, *cl, *cu, *m4a, *m4b, *bias4;
    cudaGetSymbolAddress((void**)&M, g_M);
    cudaGetSymbolAddress((void**)&T, g_T);
    cudaGetSymbolAddress((void**)&A, g_A);
    cudaGetSymbolAddress((void**)&lf1, g_lf1); cudaGetSymbolAddress((void**)&uf1, g_uf1);
    cudaGetSymbolAddress((void**)&w1, g_w1);   cudaGetSymbolAddress((void**)&bl1, g_bl1);
    cudaGetSymbolAddress((void**)&bu1, g_bu1);
    cudaGetSymbolAddress((void**)&lf2, g_lf2); cudaGetSymbolAddress((void**)&uf2, g_uf2);
    cudaGetSymbolAddress((void**)&w2, g_w2);   cudaGetSymbolAddress((void**)&bl2, g_bl2);
    cudaGetSymbolAddress((void**)&bu2, g_bu2);
    cudaGetSymbolAddress((void**)&lf3, g_lf3); cudaGetSymbolAddress((void**)&uf3, g_uf3);
    cudaGetSymbolAddress((void**)&w3, g_w3);   cudaGetSymbolAddress((void**)&bl3, g_bl3);
    cudaGetSymbolAddress((void**)&bu3, g_bu3);
    cudaGetSymbolAddress((void**)&cl, g_cl);   cudaGetSymbolAddress((void**)&cu, g_cu);
    cudaGetSymbolAddress((void**)&m4a, g_m4a); cudaGetSymbolAddress((void**)&m4b, g_m4b);
    cudaGetSymbolAddress((void**)&bias4, g_bias4);

    // ---- stage 1: concrete bounds of layer-1 pre-activations ----
    concretize_k<<<H, 256>>>(W1, DIN, l_in, u_in, b1, b1, lf1, uf1);
    spu_params_k<<<(H + 255) / 256, 256>>>(lf1, uf1, p_l1, p_u1, w1, bl1, bu1, H);

    // ---- stage 2: bounds of layer-2 pre-activations ----
    scale_bias_k<<<H, 256>>>(W2, M, w1, bl1, bu1, b2, b1, cl, cu);
    {
        dim3 g((DIN + 127) / 128, H / 128);
        sgemm_k<<<g, 256>>>(H, DIN, H, M, W1, A, nullptr);
    }
    concretize_k<<<H, 256>>>(A, DIN, l_in, u_in, cl, cu, lf2, uf2);
    spu_params_k<<<(H + 255) / 256, 256>>>(lf2, uf2, p_l2, p_u2, w2, bl2, bu2, H);

    // ---- stage 3: bounds of layer-3 pre-activations ----
    scale_bias_k<<<H, 256>>>(W3, M, w2, bl2, bu2, b3, b2, cl, cu);
    {
        dim3 g(H / 128, H / 128);
        sgemm_k<<<g, 256>>>(H, H, H, M, W2, T, nullptr);   // 17.2 GFLOP
    }
    bias_T_k<<<H, 256>>>(T, w1, bl1, bu1, b1, cl, cu);
    {
        dim3 g((DIN + 127) / 128, H / 128);
        sgemm_k<<<g, 256>>>(H, DIN, H, T, W1, A, w1);      // (T .* w1) @ W1
    }
    concretize_k<<<H, 256>>>(A, DIN, l_in, u_in, cl, cu, lf3, uf3);
    spu_params_k<<<(H + 255) / 256, 256>>>(lf3, uf3, p_l3, p_u3, w3, bl3, bu3, H);

    // ---- stage 4: final upper bounds (9 output rows) ----
    build_m4_k<<<(OUTR * H + 255) / 256, 256>>>(W4, b4, tl, m4a, bias4);
    small_bias_k<<<OUTR, 256>>>(m4a, w3, bl3, bu3, b3, bias4);
    small_gemm_k<<<(H + 127) / 128, 128>>>(H, H, m4a, w3, W3, m4b);
    small_bias_k<<<OUTR, 256>>>(m4b, w2, bl2, bu2, b2, bias4);
    small_gemm_k<<<(H + 127) / 128, 128>>>(H, H, m4b, w2, W2, m4a);
    small_bias_k<<<OUTR, 256>>>(m4a, w1, bl1, bu1, b1, bias4);
    small_gemm_k<<<(DIN + 127) / 128, 128>>>(H, DIN, m4a, w1, W1, m4b);
    final_k<<<OUTR, 256>>>(m4b, l_in, u_in, bias4, out);
}

// round 3
// speedup vs baseline: 2.0493x; 2.0493x over previous
#include <cuda_runtime.h>
#include <math.h>

#define H    2048
#define DIN  784
#define OUTR 9        // num classes (10) - 1
#define BK   16

// ---------------- scratch (device globals; no allocation allowed) ----------
__device__ float g_T[H * H];         // stage-3 intermediate (M3 @ W2)
__device__ float g_A[H * DIN];       // A2 then A3
__device__ float g_lf1[H], g_uf1[H], g_w1[H], g_bl1[H], g_bu1[H];
__device__ float g_lf2[H], g_uf2[H], g_w2[H], g_bl2[H], g_bu2[H];
__device__ float g_lf3[H], g_uf3[H], g_w3[H], g_bl3[H], g_bu3[H];
__device__ float g_cl[H], g_cu[H];
__device__ float g_m4a[OUTR * H], g_m4b[OUTR * H];
__device__ float g_bias4[OUTR];

// ---------------- helpers ---------------------------------------------------
__device__ __forceinline__ float spu_f(float x) {
    if (x >= 0.f) return x * x - 0.5f;
    float s = 1.f / (1.f + expf(x));      // sigmoid(-x)
    return s - 1.f;
}
__device__ __forceinline__ float dspu_f(float x) {
    if (x >= 0.f) return 2.f * x;
    float s = 1.f / (1.f + expf(x));
    return -s * (1.f - s);
}

__device__ __forceinline__ unsigned long long dup2(float x) {
    unsigned long long r;
    asm("mov.b64 %0, {%1, %1};" : "=l"(r) : "f"(x));
    return r;
}
__device__ __forceinline__ void ffma2(unsigned long long &d,
                                      unsigned long long a, unsigned long long b) {
    asm("fma.rn.f32x2 %0, %1, %2, %0;" : "+l"(d) : "l"(a), "l"(b));
}
union U64F2 { unsigned long long p; float2 f; };
union F4P2  { float4 v; unsigned long long p[2]; };

__device__ __forceinline__ void blk_reduce2(float &a, float &b) {
    const unsigned m = 0xffffffffu;
    #pragma unroll
    for (int o = 16; o > 0; o >>= 1) {
        a += __shfl_down_sync(m, a, o);
        b += __shfl_down_sync(m, b, o);
    }
    __shared__ float sa[8], sb[8];
    int w = threadIdx.x >> 5, l = threadIdx.x & 31;
    int nw = blockDim.x >> 5;
    if (l == 0) { sa[w] = a; sb[w] = b; }
    __syncthreads();
    if (w == 0) {
        a = (l < nw) ? sa[l] : 0.f;
        b = (l < nw) ? sb[l] : 0.f;
        #pragma unroll
        for (int o = 4; o > 0; o >>= 1) {
            a += __shfl_down_sync(m, a, o);
            b += __shfl_down_sync(m, b, o);
        }
    }
}

// ---------------- elementwise / reduction kernels ---------------------------

__global__ void concretize_k(const float* __restrict__ A, int ncols,
                             const float* __restrict__ lin, const float* __restrict__ uin,
                             const float* __restrict__ cl, const float* __restrict__ cu,
                             float* __restrict__ lf, float* __restrict__ uf) {
    int row = blockIdx.x;
    const float* a = A + (size_t)row * ncols;
    float al = 0.f, au = 0.f;
    for (int j = threadIdx.x; j < ncols; j += blockDim.x) {
        float v = a[j], l = lin[j], u = uin[j];
        float p = fmaxf(v, 0.f), n = fminf(v, 0.f);
        al += p * l + n * u;
        au += p * u + n * l;
    }
    blk_reduce2(al, au);
    if (threadIdx.x == 0) { lf[row] = al + cl[row]; uf[row] = au + cu[row]; }
}

__global__ void spu_params_k(const float* __restrict__ lf, const float* __restrict__ uf,
                             const float* __restrict__ pl, const float* __restrict__ pu,
                             float* __restrict__ w, float* __restrict__ bl,
                             float* __restrict__ bu, int n) {
    int i = blockIdx.x * blockDim.x + threadIdx.x;
    if (i >= n) return;
    float l = lf[i], u = uf[i];
    float k1 = dspu_f(l), k2 = dspu_f(u);
    float klo = fminf(k1, k2), khi = fmaxf(k1, k2);
    float wl = fminf(fmaxf(pl[i], klo), khi);
    float wu = fminf(fmaxf(pu[i], klo), khi);
    float p0 = l, p1 = u, p2 = 0.5f * (l + u), p3 = fminf(fmaxf(0.f, l), u);
    float s0 = spu_f(p0), s1 = spu_f(p1), s2 = spu_f(p2), s3 = spu_f(p3);
    float bl_ = fminf(fminf(s0 - wl * p0, s1 - wl * p1), fminf(s2 - wl * p2, s3 - wl * p3));
    float bu_ = fmaxf(fmaxf(s0 - wu * p0, s1 - wu * p1), fmaxf(s2 - wu * p2, s3 - wu * p3));
    w[i] = wl; bl[i] = bl_; bu[i] = bu_;
}

// cl[i] = bthis[i] + sum_j pos(W)*blprev + neg(W)*buprev + W*wprev*bprev ; cu symmetric
__global__ void bias2_k(const float* __restrict__ W,
                        const float* __restrict__ wprev,
                        const float* __restrict__ blprev, const float* __restrict__ buprev,
                        const float* __restrict__ bthis, const float* __restrict__ bprev,
                        float* __restrict__ cl, float* __restrict__ cu) {
    int row = blockIdx.x;
    const float* wr = W + (size_t)row * H;
    float al = 0.f, au = 0.f;
    for (int j = threadIdx.x; j < H; j += blockDim.x) {
        float v = wr[j];
        float p = fmaxf(v, 0.f), n = fminf(v, 0.f);
        float sb = v * wprev[j] * bprev[j];
        al += p * blprev[j] + n * buprev[j] + sb;
        au += p * buprev[j] + n * blprev[j] + sb;
    }
    blk_reduce2(al, au);
    if (threadIdx.x == 0) { cl[row] = bthis[row] + al; cu[row] = bthis[row] + au; }
}

// cl[i] += sum_j pos(T)*bl + neg(T)*bu + T*w*b ; cu symmetric
__global__ void bias_T_k(const float* __restrict__ T,
                         const float* __restrict__ w, const float* __restrict__ bl,
                         const float* __restrict__ bu, const float* __restrict__ b,
                         float* __restrict__ cl, float* __restrict__ cu) {
    int row = blockIdx.x;
    const float* tr = T + (size_t)row * H;
    float al = 0.f, au = 0.f;
    for (int j = threadIdx.x; j < H; j += blockDim.x) {
        float v = tr[j];
        float p = fmaxf(v, 0.f), n = fminf(v, 0.f);
        float sb = v * w[j] * b[j];
        al += p * bl[j] + n * bu[j] + sb;
        au += p * bu[j] + n * bl[j] + sb;
    }
    blk_reduce2(al, au);
    if (threadIdx.x == 0) { cl[row] += al; cu[row] += au; }
}

// ---------------- FFMA2 GEMMs ------------------------------------------------
// C[H x H] = (A .* asc_cols) @ B, all dims H. 128x128 tile, 8x8 micro, BK=16,
// double-buffered, packed f32x2 FMA (pairs along j).
__global__ __launch_bounds__(256, 2)
void gemm_big_k(const float* __restrict__ A, const float* __restrict__ asc,
                const float* __restrict__ B, float* __restrict__ C) {
    __shared__ float As[2][BK][128];
    __shared__ float Bs[2][BK][128];
    int tid = threadIdx.x;
    int brow = blockIdx.y * 128, bcol = blockIdx.x * 128;
    int tx = tid & 15, ty = tid >> 4;

    int a_row = tid & 127;
    int a_kq0 = tid >> 7;          // 0..1 ; +2 for i=1
    int b_kr  = tid >> 5;          // 0..7 ; +8 for i=1
    int b_c4  = (tid & 31) * 4;

    float4 pa[2], pb[2], ps[2];
    const float* Abase = A + (size_t)(brow + a_row) * H;

    unsigned long long acc[8][4];
    #pragma unroll
    for (int i = 0; i < 8; i++)
        #pragma unroll
        for (int j = 0; j < 4; j++) acc[i][j] = 0ull;

    // prologue: tile 0
    #pragma unroll
    for (int i = 0; i < 2; i++) {
        int kq = a_kq0 + 2 * i;
        pa[i] = *(const float4*)(Abase + kq * 4);
        ps[i] = *(const float4*)(asc + kq * 4);
        pb[i] = *(const float4*)(B + (size_t)(b_kr + 8 * i) * H + bcol + b_c4);
    }
    #pragma unroll
    for (int i = 0; i < 2; i++) {
        int kq = a_kq0 + 2 * i;
        As[0][kq * 4 + 0][a_row] = pa[i].x * ps[i].x;
        As[0][kq * 4 + 1][a_row] = pa[i].y * ps[i].y;
        As[0][kq * 4 + 2][a_row] = pa[i].z * ps[i].z;
        As[0][kq * 4 + 3][a_row] = pa[i].w * ps[i].w;
        *(float4*)&Bs[0][b_kr + 8 * i][b_c4] = pb[i];
    }
    __syncthreads();

    const int NKB = H / BK;
    for (int kb = 0; kb < NKB; kb++) {
        int cur = kb & 1;
        if (kb + 1 < NKB) {
            int k0 = (kb + 1) * BK;
            #pragma unroll
            for (int i = 0; i < 2; i++) {
                int kq = a_kq0 + 2 * i;
                pa[i] = *(const float4*)(Abase + k0 + kq * 4);
                ps[i] = *(const float4*)(asc + k0 + kq * 4);
                pb[i] = *(const float4*)(B + (size_t)(k0 + b_kr + 8 * i) * H + bcol + b_c4);
            }
        }
        #pragma unroll
        for (int kk = 0; kk < BK; kk++) {
            float4 a0 = *(const float4*)&As[cur][kk][ty * 8];
            float4 a1 = *(const float4*)&As[cur][kk][ty * 8 + 4];
            F4P2 b0, b1;
            b0.v = *(const float4*)&Bs[cur][kk][tx * 8];
            b1.v = *(const float4*)&Bs[cur][kk][tx * 8 + 4];
            unsigned long long ad[8];
            ad[0] = dup2(a0.x); ad[1] = dup2(a0.y); ad[2] = dup2(a0.z); ad[3] = dup2(a0.w);
            ad[4] = dup2(a1.x); ad[5] = dup2(a1.y); ad[6] = dup2(a1.z); ad[7] = dup2(a1.w);
            unsigned long long bp0 = b0.p[0], bp1 = b0.p[1], bp2 = b1.p[0], bp3 = b1.p[1];
            #pragma unroll
            for (int i = 0; i < 8; i++) {
                ffma2(acc[i][0], ad[i], bp0);
                ffma2(acc[i][1], ad[i], bp1);
                ffma2(acc[i][2], ad[i], bp2);
                ffma2(acc[i][3], ad[i], bp3);
            }
        }
        if (kb + 1 < NKB) {
            int nxt = cur ^ 1;
            #pragma unroll
            for (int i = 0; i < 2; i++) {
                int kq = a_kq0 + 2 * i;
                As[nxt][kq * 4 + 0][a_row] = pa[i].x * ps[i].x;
                As[nxt][kq * 4 + 1][a_row] = pa[i].y * ps[i].y;
                As[nxt][kq * 4 + 2][a_row] = pa[i].z * ps[i].z;
                As[nxt][kq * 4 + 3][a_row] = pa[i].w * ps[i].w;
                *(float4*)&Bs[nxt][b_kr + 8 * i][b_c4] = pb[i];
            }
        }
        __syncthreads();
    }

    #pragma unroll
    for (int i = 0; i < 8; i++) {
        int gr = brow + ty * 8 + i;
        U64F2 u0, u1, u2, u3;
        u0.p = acc[i][0]; u1.p = acc[i][1]; u2.p = acc[i][2]; u3.p = acc[i][3];
        float* cp = C + (size_t)gr * H + bcol + tx * 8;
        *(float4*)cp       = make_float4(u0.f.x, u0.f.y, u1.f.x, u1.f.y);
        *(float4*)(cp + 4) = make_float4(u2.f.x, u2.f.y, u3.f.x, u3.f.y);
    }
}

// C[H x DIN] = (A .* asc_cols) @ B[H x DIN]. 128x64 tile, 8x4 micro (pairs along i).
__global__ __launch_bounds__(256, 2)
void gemm_mid_k(const float* __restrict__ A, const float* __restrict__ asc,
                const float* __restrict__ B, float* __restrict__ C) {
    __shared__ float As[2][BK][128];
    __shared__ float Bs[2][BK][64];
    int tid = threadIdx.x;
    int brow = blockIdx.y * 128, bcol = blockIdx.x * 64;
    int tx = tid & 15, ty = tid >> 4;

    int a_row = tid & 127;
    int a_kq0 = tid >> 7;
    int b_kr  = tid >> 4;          // 0..15
    int b_c4  = (tid & 15) * 4;
    bool bvalid = (bcol + b_c4) < DIN;

    float4 pa[2], ps[2], pb;
    const float* Abase = A + (size_t)(brow + a_row) * H;

    unsigned long long acc[4][4];
    #pragma unroll
    for (int i = 0; i < 4; i++)
        #pragma unroll
        for (int j = 0; j < 4; j++) acc[i][j] = 0ull;

    #pragma unroll
    for (int i = 0; i < 2; i++) {
        int kq = a_kq0 + 2 * i;
        pa[i] = *(const float4*)(Abase + kq * 4);
        ps[i] = *(const float4*)(asc + kq * 4);
    }
    pb = bvalid ? *(const float4*)(B + (size_t)b_kr * DIN + bcol + b_c4)
                : make_float4(0.f, 0.f, 0.f, 0.f);
    #pragma unroll
    for (int i = 0; i < 2; i++) {
        int kq = a_kq0 + 2 * i;
        As[0][kq * 4 + 0][a_row] = pa[i].x * ps[i].x;
        As[0][kq * 4 + 1][a_row] = pa[i].y * ps[i].y;
        As[0][kq * 4 + 2][a_row] = pa[i].z * ps[i].z;
        As[0][kq * 4 + 3][a_row] = pa[i].w * ps[i].w;
    }
    *(float4*)&Bs[0][b_kr][b_c4] = pb;
    __syncthreads();

    const int NKB = H / BK;
    for (int kb = 0; kb < NKB; kb++) {
        int cur = kb & 1;
        if (kb + 1 < NKB) {
            int k0 = (kb + 1) * BK;
            #pragma unroll
            for (int i = 0; i < 2; i++) {
                int kq = a_kq0 + 2 * i;
                pa[i] = *(const float4*)(Abase + k0 + kq * 4);
                ps[i] = *(const float4*)(asc + k0 + kq * 4);
            }
            pb = bvalid ? *(const float4*)(B + (size_t)(k0 + b_kr) * DIN + bcol + b_c4)
                        : make_float4(0.f, 0.f, 0.f, 0.f);
        }
        #pragma unroll
        for (int kk = 0; kk < BK; kk++) {
            F4P2 a0, a1;
            a0.v = *(const float4*)&As[cur][kk][ty * 8];
            a1.v = *(const float4*)&As[cur][kk][ty * 8 + 4];
            float4 b = *(const float4*)&Bs[cur][kk][tx * 4];
            unsigned long long ap[4] = { a0.p[0], a0.p[1], a1.p[0], a1.p[1] };
            unsigned long long bd[4] = { dup2(b.x), dup2(b.y), dup2(b.z), dup2(b.w) };
            #pragma unroll
            for (int i = 0; i < 4; i++) {
                ffma2(acc[i][0], ap[i], bd[0]);
                ffma2(acc[i][1], ap[i], bd[1]);
                ffma2(acc[i][2], ap[i], bd[2]);
                ffma2(acc[i][3], ap[i], bd[3]);
            }
        }
        if (kb + 1 < NKB) {
            int nxt = cur ^ 1;
            #pragma unroll
            for (int i = 0; i < 2; i++) {
                int kq = a_kq0 + 2 * i;
                As[nxt][kq * 4 + 0][a_row] = pa[i].x * ps[i].x;
                As[nxt][kq * 4 + 1][a_row] = pa[i].y * ps[i].y;
                As[nxt][kq * 4 + 2][a_row] = pa[i].z * ps[i].z;
                As[nxt][kq * 4 + 3][a_row] = pa[i].w * ps[i].w;
            }
            *(float4*)&Bs[nxt][b_kr][b_c4] = pb;
        }
        __syncthreads();
    }

    int gc = bcol + tx * 4;
    if (gc < DIN) {
        #pragma unroll
        for (int i2 = 0; i2 < 4; i2++) {
            int r0 = brow + ty * 8 + 2 * i2;
            U64F2 u0, u1, u2, u3;
            u0.p = acc[i2][0]; u1.p = acc[i2][1]; u2.p = acc[i2][2]; u3.p = acc[i2][3];
            *(float4*)(C + (size_t)r0 * DIN + gc) =
                make_float4(u0.f.x, u1.f.x, u2.f.x, u3.f.x);
            *(float4*)(C + (size_t)(r0 + 1) * DIN + gc) =
                make_float4(u0.f.y, u1.f.y, u2.f.y, u3.f.y);
        }
    }
}

// ---- output stage (9 rows) ----
__global__ void build_m4_k(const float* __restrict__ W4, const float* __restrict__ b4,
                           const int* __restrict__ tl, float* __restrict__ M,
                           float* __restrict__ bias) {
    int t = *tl;
    int idx = blockIdx.x * blockDim.x + threadIdx.x;
    if (idx < OUTR * H) {
        int r = idx / H, j = idx % H;
        int c = (r < t) ? r : r + 1;
        M[idx] = W4[(size_t)c * H + j] - W4[(size_t)t * H + j];
    }
    if (idx < OUTR) {
        int c = (idx < t) ? idx : idx + 1;
        bias[idx] = b4[c] - b4[t];
    }
}

__global__ void small_bias_k(const float* __restrict__ A,
                             const float* __restrict__ w, const float* __restrict__ bl,
                             const float* __restrict__ bu, const float* __restrict__ bnext,
                             float* __restrict__ bias) {
    int r = blockIdx.x;
    const float* a = A + (size_t)r * H;
    float au = 0.f, dummy = 0.f;
    for (int j = threadIdx.x; j < H; j += blockDim.x) {
        float v = a[j];
        float p = fmaxf(v, 0.f), n = fminf(v, 0.f);
        au += p * bu[j] + n * bl[j] + v * w[j] * bnext[j];
    }
    blk_reduce2(au, dummy);
    if (threadIdx.x == 0) bias[r] += au;
}

__global__ void zero_k(float* __restrict__ p, int n) {
    int i = blockIdx.x * blockDim.x + threadIdx.x;
    if (i < n) p[i] = 0.f;
}

// C[OUTR x N] += (A[OUTR x K] .* asc_cols) @ B[K x N], split-K via blockIdx.y
#define SG_CHUNK 256
__global__ void small_gemm_k(int K, int N, const float* __restrict__ A,
                             const float* __restrict__ ascale,
                             const float* __restrict__ B, float* __restrict__ C) {
    __shared__ float sA[OUTR * SG_CHUNK];
    int k0 = blockIdx.y * SG_CHUNK;
    int n = blockIdx.x * blockDim.x + threadIdx.x;
    for (int idx = threadIdx.x; idx < OUTR * SG_CHUNK; idx += blockDim.x) {
        int r = idx / SG_CHUNK, kk = idx % SG_CHUNK;
        sA[idx] = A[(size_t)r * K + k0 + kk] * ascale[k0 + kk];
    }
    __syncthreads();
    if (n >= N) return;
    float acc[OUTR];
    #pragma unroll
    for (int r = 0; r < OUTR; r++) acc[r] = 0.f;
    #pragma unroll 4
    for (int kk = 0; kk < SG_CHUNK; kk++) {
        float bv = B[(size_t)(k0 + kk) * N + n];
        #pragma unroll
        for (int r = 0; r < OUTR; r++) acc[r] += sA[r * SG_CHUNK + kk] * bv;
    }
    #pragma unroll
    for (int r = 0; r < OUTR; r++) atomicAdd(&C[(size_t)r * N + n], acc[r]);
}

__global__ void final_k(const float* __restrict__ M, const float* __restrict__ lin,
                        const float* __restrict__ uin, const float* __restrict__ bias,
                        float* __restrict__ out) {
    int r = blockIdx.x;
    const float* a = M + (size_t)r * DIN;
    float au = 0.f, dummy = 0.f;
    for (int j = threadIdx.x; j < DIN; j += blockDim.x) {
        float v = a[j];
        au += fmaxf(v, 0.f) * uin[j] + fminf(v, 0.f) * lin[j];
    }
    blk_reduce2(au, dummy);
    if (threadIdx.x == 0) out[r] = au + bias[r];
}

// ---------------- launch -----------------------------------------------------
extern "C" void kernel_launch(void* const* d_in, const int* in_sizes, int n_in,
                              void* d_out, int out_size) {
    const float* W1 = (const float*)d_in[0];
    const float* b1 = (const float*)d_in[1];
    const float* W2 = (const float*)d_in[2];
    const float* b2 = (const float*)d_in[3];
    const float* W3 = (const float*)d_in[4];
    const float* b3 = (const float*)d_in[5];
    const float* W4 = (const float*)d_in[6];
    const float* b4 = (const float*)d_in[7];
    const float* l_in = (const float*)d_in[8];
    const float* u_in = (const float*)d_in[9];
    const float* p_l1 = (const float*)d_in[10];
    const float* p_u1 = (const float*)d_in[11];
    const float* p_l2 = (const float*)d_in[12];
    const float* p_u2 = (const float*)d_in[13];
    const float* p_l3 = (const float*)d_in[14];
    const float* p_u3 = (const float*)d_in[15];
    const int* tl = (const int*)d_in[16];
    float* out = (float*)d_out;

    float *T, *A, *lf1, *uf1, *w1, *bl1, *bu1, *lf2, *uf2, *w2, *bl2, *bu2;
    float *lf3, *uf3, *w3, *bl3, *bu3, *cl, *cu, *m4a, *m4b, *bias4;
    cudaGetSymbolAddress((void**)&T, g_T);
    cudaGetSymbolAddress((void**)&A, g_A);
    cudaGetSymbolAddress((void**)&lf1, g_lf1); cudaGetSymbolAddress((void**)&uf1, g_uf1);
    cudaGetSymbolAddress((void**)&w1, g_w1);   cudaGetSymbolAddress((void**)&bl1, g_bl1);
    cudaGetSymbolAddress((void**)&bu1, g_bu1);
    cudaGetSymbolAddress((void**)&lf2, g_lf2); cudaGetSymbolAddress((void**)&uf2, g_uf2);
    cudaGetSymbolAddress((void**)&w2, g_w2);   cudaGetSymbolAddress((void**)&bl2, g_bl2);
    cudaGetSymbolAddress((void**)&bu2, g_bu2);
    cudaGetSymbolAddress((void**)&lf3, g_lf3); cudaGetSymbolAddress((void**)&uf3, g_uf3);
    cudaGetSymbolAddress((void**)&w3, g_w3);   cudaGetSymbolAddress((void**)&bl3, g_bl3);
    cudaGetSymbolAddress((void**)&bu3, g_bu3);
    cudaGetSymbolAddress((void**)&cl, g_cl);   cudaGetSymbolAddress((void**)&cu, g_cu);
    cudaGetSymbolAddress((void**)&m4a, g_m4a); cudaGetSymbolAddress((void**)&m4b, g_m4b);
    cudaGetSymbolAddress((void**)&bias4, g_bias4);

    dim3 gmid((DIN + 63) / 64, H / 128);      // 13 x 16
    dim3 gbig(H / 128, H / 128);              // 16 x 16

    // ---- stage 1 ----
    concretize_k<<<H, 256>>>(W1, DIN, l_in, u_in, b1, b1, lf1, uf1);
    spu_params_k<<<(H + 255) / 256, 256>>>(lf1, uf1, p_l1, p_u1, w1, bl1, bu1, H);

    // ---- stage 2 ----
    bias2_k<<<H, 256>>>(W2, w1, bl1, bu1, b2, b1, cl, cu);
    gemm_mid_k<<<gmid, 256>>>(W2, w1, W1, A);           // (W2 .* w1) @ W1
    concretize_k<<<H, 256>>>(A, DIN, l_in, u_in, cl, cu, lf2, uf2);
    spu_params_k<<<(H + 255) / 256, 256>>>(lf2, uf2, p_l2, p_u2, w2, bl2, bu2, H);

    // ---- stage 3 ----
    bias2_k<<<H, 256>>>(W3, w2, bl2, bu2, b3, b2, cl, cu);
    gemm_big_k<<<gbig, 256>>>(W3, w2, W2, T);           // (W3 .* w2) @ W2
    bias_T_k<<<H, 256>>>(T, w1, bl1, bu1, b1, cl, cu);
    gemm_mid_k<<<gmid, 256>>>(T, w1, W1, A);            // (T .* w1) @ W1
    concretize_k<<<H, 256>>>(A, DIN, l_in, u_in, cl, cu, lf3, uf3);
    spu_params_k<<<(H + 255) / 256, 256>>>(lf3, uf3, p_l3, p_u3, w3, bl3, bu3, H);

    // ---- stage 4: output chain (9 rows) ----
    build_m4_k<<<(OUTR * H + 255) / 256, 256>>>(W4, b4, tl, m4a, bias4);
    small_bias_k<<<OUTR, 256>>>(m4a, w3, bl3, bu3, b3, bias4);
    zero_k<<<(OUTR * H + 255) / 256, 256>>>(m4b, OUTR * H);
    small_gemm_k<<<dim3((H + 127) / 128, H / SG_CHUNK), 128>>>(H, H, m4a, w3, W3, m4b);
    small_bias_k<<<OUTR, 256>>>(m4b, w2, bl2, bu2, b2, bias4);
    zero_k<<<(OUTR * H + 255) / 256, 256>>>(m4a, OUTR * H);
    small_gemm_k<<<dim3((H + 127) / 128, H / SG_CHUNK), 128>>>(H, H, m4b, w2, W2, m4a);
    small_bias_k<<<OUTR, 256>>>(m4a, w1, bl1, bu1, b1, bias4);
    zero_k<<<(OUTR * DIN + 255) / 256, 256>>>(m4b, OUTR * DIN);
    small_gemm_k<<<dim3((DIN + 127) / 128, H / SG_CHUNK), 128>>>(H, DIN, m4a, w1, W1, m4b);
    final_k<<<OUTR, 256>>>(m4b, l_in, u_in, bias4, out);
}

// round 5
// speedup vs baseline: 3.6507x; 1.7815x over previous
#include <cuda_runtime.h>
#include <cuda_bf16.h>
#include <math.h>
#include <stdint.h>

#define H     2048
#define DIN   784
#define OUTR  9
#define KTOT  2048
#define KC    64
#define NCHUNK (KTOT / KC)          // 32
#define TILEB  16384                // 128 rows * 128B (128x64 bf16)
#define BUFB   (4 * TILEB)          // 64KB per stage (Ahi,Alo,Bhi,Blo)
#define DSMEM  (2 * BUFB + 1024)
#define NPAD1  896                  // DIN padded to 128-multiple

// ---------------- scratch (device globals) ----------------------------------
__device__ float g_T[H * H];
__device__ float g_A[H * DIN];
__device__ __nv_bfloat16 g_Ahi[H * H], g_Alo[H * H];
__device__ __nv_bfloat16 g_W1t_hi[NPAD1 * KTOT], g_W1t_lo[NPAD1 * KTOT];  // pad rows stay 0
__device__ __nv_bfloat16 g_W2t_hi[H * KTOT], g_W2t_lo[H * KTOT];
__device__ float g_lf1[H], g_uf1[H], g_w1[H], g_bl1[H], g_bu1[H];
__device__ float g_lf2[H], g_uf2[H], g_w2[H], g_bl2[H], g_bu2[H];
__device__ float g_lf3[H], g_uf3[H], g_w3[H], g_bl3[H], g_bu3[H];
__device__ float g_cl[H], g_cu[H];
__device__ float g_m4a[OUTR * H], g_m4b[OUTR * H];
__device__ float g_bias4[OUTR];

// ---------------- PTX helpers ------------------------------------------------
__device__ __forceinline__ uint32_t smem_u32(const void* p) {
    uint32_t a;
    asm("{ .reg .u64 t; cvta.to.shared.u64 t, %1; cvt.u32.u64 %0, t; }" : "=r"(a) : "l"(p));
    return a;
}
#define SWZ128(o)  ((o) ^ (((o) >> 3) & 0x70))
#define CP_ASYNC16(dst, gsrc) \
    asm volatile("cp.async.cg.shared.global [%0], [%1], 16;" :: "r"(dst), "l"(gsrc))
#define CP_COMMIT() asm volatile("cp.async.commit_group;" ::: "memory")
#define CP_WAIT(n)  asm volatile("cp.async.wait_group %0;" :: "n"(n) : "memory")
#define LDSM_X4(r0, r1, r2, r3, addr) \
    asm volatile("ldmatrix.sync.aligned.m8n8.x4.shared.b16 {%0,%1,%2,%3}, [%4];" \
        : "=r"(r0), "=r"(r1), "=r"(r2), "=r"(r3) : "r"(addr))
#define MMA16816(d, a, b) \
    asm volatile("mma.sync.aligned.m16n8k16.row.col.f32.bf16.bf16.f32 " \
        "{%0,%1,%2,%3}, {%4,%5,%6,%7}, {%8,%9}, {%0,%1,%2,%3};" \
        : "+f"((d)[0]), "+f"((d)[1]), "+f"((d)[2]), "+f"((d)[3]) \
        : "r"((a)[0]), "r"((a)[1]), "r"((a)[2]), "r"((a)[3]), "r"((b)[0]), "r"((b)[1]))

// ---------------- misc helpers ----------------------------------------------
__device__ __forceinline__ float spu_f(float x) {
    if (x >= 0.f) return x * x - 0.5f;
    float s = 1.f / (1.f + expf(x));
    return s - 1.f;
}
__device__ __forceinline__ float dspu_f(float x) {
    if (x >= 0.f) return 2.f * x;
    float s = 1.f / (1.f + expf(x));
    return -s * (1.f - s);
}
__device__ __forceinline__ void blk_reduce2(float &a, float &b) {
    const unsigned m = 0xffffffffu;
    #pragma unroll
    for (int o = 16; o > 0; o >>= 1) {
        a += __shfl_down_sync(m, a, o);
        b += __shfl_down_sync(m, b, o);
    }
    __shared__ float sa[8], sb[8];
    int w = threadIdx.x >> 5, l = threadIdx.x & 31;
    int nw = blockDim.x >> 5;
    if (l == 0) { sa[w] = a; sb[w] = b; }
    __syncthreads();
    if (w == 0) {
        a = (l < nw) ? sa[l] : 0.f;
        b = (l < nw) ? sb[l] : 0.f;
        #pragma unroll
        for (int o = 4; o > 0; o >>= 1) {
            a += __shfl_down_sync(m, a, o);
            b += __shfl_down_sync(m, b, o);
        }
    }
}

// ---------------- elementwise / reduction kernels ---------------------------
__global__ void concretize_k(const float* __restrict__ A, int ncols,
                             const float* __restrict__ lin, const float* __restrict__ uin,
                             const float* __restrict__ cl, const float* __restrict__ cu,
                             float* __restrict__ lf, float* __restrict__ uf) {
    int row = blockIdx.x;
    const float* a = A + (size_t)row * ncols;
    float al = 0.f, au = 0.f;
    for (int j = threadIdx.x; j < ncols; j += blockDim.x) {
        float v = a[j], l = lin[j], u = uin[j];
        float p = fmaxf(v, 0.f), n = fminf(v, 0.f);
        al += p * l + n * u;
        au += p * u + n * l;
    }
    blk_reduce2(al, au);
    if (threadIdx.x == 0) { lf[row] = al + cl[row]; uf[row] = au + cu[row]; }
}

__global__ void spu_params_k(const float* __restrict__ lf, const float* __restrict__ uf,
                             const float* __restrict__ pl, const float* __restrict__ pu,
                             float* __restrict__ w, float* __restrict__ bl,
                             float* __restrict__ bu, int n) {
    int i = blockIdx.x * blockDim.x + threadIdx.x;
    if (i >= n) return;
    float l = lf[i], u = uf[i];
    float k1 = dspu_f(l), k2 = dspu_f(u);
    float klo = fminf(k1, k2), khi = fmaxf(k1, k2);
    float wl = fminf(fmaxf(pl[i], klo), khi);
    float wu = fminf(fmaxf(pu[i], klo), khi);
    float p0 = l, p1 = u, p2 = 0.5f * (l + u), p3 = fminf(fmaxf(0.f, l), u);
    float s0 = spu_f(p0), s1 = spu_f(p1), s2 = spu_f(p2), s3 = spu_f(p3);
    float bl_ = fminf(fminf(s0 - wl * p0, s1 - wl * p1), fminf(s2 - wl * p2, s3 - wl * p3));
    float bu_ = fmaxf(fmaxf(s0 - wu * p0, s1 - wu * p1), fmaxf(s2 - wu * p2, s3 - wu * p3));
    w[i] = wl; bl[i] = bl_; bu[i] = bu_;
}

// bias for (W .* wprev) stage, fused with bf16 hi/lo split of M = W .* wprev
__global__ void bias2conv_k(const float* __restrict__ W,
                            const float* __restrict__ wprev,
                            const float* __restrict__ blprev, const float* __restrict__ buprev,
                            const float* __restrict__ bthis, const float* __restrict__ bprev,
                            float* __restrict__ cl, float* __restrict__ cu,
                            __nv_bfloat16* __restrict__ hi, __nv_bfloat16* __restrict__ lo) {
    int row = blockIdx.x;
    const float* wr = W + (size_t)row * H;
    __nv_bfloat16* hr = hi + (size_t)row * H;
    __nv_bfloat16* lr = lo + (size_t)row * H;
    float al = 0.f, au = 0.f;
    for (int j = threadIdx.x; j < H; j += blockDim.x) {
        float v = wr[j];
        float p = fmaxf(v, 0.f), n = fminf(v, 0.f);
        float m = v * wprev[j];
        al += p * blprev[j] + n * buprev[j] + m * bprev[j];
        au += p * buprev[j] + n * blprev[j] + m * bprev[j];
        __nv_bfloat16 h = __float2bfloat16(m);
        hr[j] = h;
        lr[j] = __float2bfloat16(m - __bfloat162float(h));
    }
    blk_reduce2(al, au);
    if (threadIdx.x == 0) { cl[row] = bthis[row] + al; cu[row] = bthis[row] + au; }
}

// bias accumulation for T stage, fused with split of T .* w
__global__ void biasTconv_k(const float* __restrict__ T,
                            const float* __restrict__ w, const float* __restrict__ bl,
                            const float* __restrict__ bu, const float* __restrict__ b,
                            float* __restrict__ cl, float* __restrict__ cu,
                            __nv_bfloat16* __restrict__ hi, __nv_bfloat16* __restrict__ lo) {
    int row = blockIdx.x;
    const float* tr = T + (size_t)row * H;
    __nv_bfloat16* hr = hi + (size_t)row * H;
    __nv_bfloat16* lr = lo + (size_t)row * H;
    float al = 0.f, au = 0.f;
    for (int j = threadIdx.x; j < H; j += blockDim.x) {
        float v = tr[j];
        float p = fmaxf(v, 0.f), n = fminf(v, 0.f);
        float m = v * w[j];
        al += p * bl[j] + n * bu[j] + m * b[j];
        au += p * bu[j] + n * bl[j] + m * b[j];
        __nv_bfloat16 h = __float2bfloat16(m);
        hr[j] = h;
        lr[j] = __float2bfloat16(m - __bfloat162float(h));
    }
    blk_reduce2(al, au);
    if (threadIdx.x == 0) { cl[row] += al; cu[row] += au; }
}

// B [K x N] fp32 row-major -> Bt_hi/lo [Npad x K] bf16 (rows >= N stay zero)
__global__ void transp_conv_k(const float* __restrict__ B, int N,
                              __nv_bfloat16* __restrict__ thi, __nv_bfloat16* __restrict__ tlo) {
    __shared__ float t[32][33];
    int k0 = blockIdx.x * 32, n0 = blockIdx.y * 32;
    int x = threadIdx.x, y = threadIdx.y;       // 32 x 8
    for (int yy = y; yy < 32; yy += 8) {
        int n = n0 + x;
        t[yy][x] = (n < N) ? B[(size_t)(k0 + yy) * N + n] : 0.f;
    }
    __syncthreads();
    for (int yy = y; yy < 32; yy += 8) {
        int n = n0 + yy, k = k0 + x;
        if (n < N) {
            float v = t[x][yy];
            __nv_bfloat16 h = __float2bfloat16(v);
            thi[(size_t)n * KTOT + k] = h;
            tlo[(size_t)n * KTOT + k] = __float2bfloat16(v - __bfloat162float(h));
        }
    }
}

// ---------------- mma.sync split-bf16 GEMM -----------------------------------
// C[128*by:+128, 128*bx:+128] = (Ahi+Alo)[rows,K] @ (Bhi+Blo)[cols,K]^T (3 products)
__global__ __launch_bounds__(256, 1)
void gemm_mma_k(const __nv_bfloat16* __restrict__ Ahi, const __nv_bfloat16* __restrict__ Alo,
                const __nv_bfloat16* __restrict__ Bhi, const __nv_bfloat16* __restrict__ Blo,
                float* __restrict__ C, int Ncols, int ldc) {
    extern __shared__ char dsm[];
    uint32_t raw = smem_u32(dsm);
    uint32_t dbase = (raw + 1023) & ~1023u;

    int tid = threadIdx.x, wid = tid >> 5, lane = tid & 31;
    int brow = blockIdx.y * 128, bcol = blockIdx.x * 128;
    int wm = (wid >> 2) * 64, wn = (wid & 3) * 32;

    // ---- staging map (cp.async) ----
    int lrow = tid >> 1, useg = (tid & 1) * 4;
    const __nv_bfloat16* bp[4] = {
        Ahi + (size_t)(brow + lrow) * KTOT, Alo + (size_t)(brow + lrow) * KTOT,
        Bhi + (size_t)(bcol + lrow) * KTOT, Blo + (size_t)(bcol + lrow) * KTOT };
    uint32_t soff[4];
    #pragma unroll
    for (int u = 0; u < 4; u++) soff[u] = SWZ128((uint32_t)(lrow * 128 + (useg + u) * 16));

    float acc[4][4][4];
    #pragma unroll
    for (int mt = 0; mt < 4; mt++)
        #pragma unroll
        for (int nt = 0; nt < 4; nt++)
            #pragma unroll
            for (int q = 0; q < 4; q++) acc[mt][nt][q] = 0.f;

    // ldmatrix per-lane row/seg components
    int l15 = lane & 15, lhi = lane >> 4;

    // preload chunk 0
    #pragma unroll
    for (int t = 0; t < 4; t++) {
        uint32_t dst = dbase + t * TILEB;
        unsigned long long g = (unsigned long long)__cvta_generic_to_global(bp[t]);
        #pragma unroll
        for (int u = 0; u < 4; u++)
            CP_ASYNC16(dst + soff[u], g + (unsigned long long)((useg + u) * 16));
    }
    CP_COMMIT();

    for (int chunk = 0; chunk < NCHUNK; chunk++) {
        int buf = chunk & 1;
        if (chunk + 1 < NCHUNK) {
            int k0 = (chunk + 1) * KC;
            #pragma unroll
            for (int t = 0; t < 4; t++) {
                uint32_t dst = dbase + (buf ^ 1) * BUFB + t * TILEB;
                unsigned long long g =
                    (unsigned long long)__cvta_generic_to_global(bp[t] + k0);
                #pragma unroll
                for (int u = 0; u < 4; u++)
                    CP_ASYNC16(dst + soff[u], g + (unsigned long long)((useg + u) * 16));
            }
            CP_COMMIT();
            CP_WAIT(1);
        } else {
            CP_WAIT(0);
        }
        __syncthreads();

        uint32_t ah_b = dbase + buf * BUFB + 0 * TILEB;
        uint32_t al_b = dbase + buf * BUFB + 1 * TILEB;
        uint32_t bh_b = dbase + buf * BUFB + 2 * TILEB;
        uint32_t bl_b = dbase + buf * BUFB + 3 * TILEB;

        #pragma unroll
        for (int kb = 0; kb < 4; kb++) {
            uint32_t kbyte = (uint32_t)(kb * 32 + lhi * 16);
            uint32_t ahi_f[4][4], alo_f[4][4], bhi_f[4][2], blo_f[4][2];
            #pragma unroll
            for (int mt = 0; mt < 4; mt++) {
                uint32_t off = SWZ128((uint32_t)((wm + mt * 16 + l15) * 128) + kbyte);
                LDSM_X4(ahi_f[mt][0], ahi_f[mt][1], ahi_f[mt][2], ahi_f[mt][3], ah_b + off);
                LDSM_X4(alo_f[mt][0], alo_f[mt][1], alo_f[mt][2], alo_f[mt][3], al_b + off);
            }
            #pragma unroll
            for (int p = 0; p < 2; p++) {
                uint32_t off = SWZ128((uint32_t)((wn + p * 16 + l15) * 128) + kbyte);
                uint32_t r0, r1, r2, r3;
                LDSM_X4(r0, r1, r2, r3, bh_b + off);
                bhi_f[2 * p][0] = r0; bhi_f[2 * p][1] = r2;
                bhi_f[2 * p + 1][0] = r1; bhi_f[2 * p + 1][1] = r3;
                LDSM_X4(r0, r1, r2, r3, bl_b + off);
                blo_f[2 * p][0] = r0; blo_f[2 * p][1] = r2;
                blo_f[2 * p + 1][0] = r1; blo_f[2 * p + 1][1] = r3;
            }
            #pragma unroll
            for (int mt = 0; mt < 4; mt++)
                #pragma unroll
                for (int nt = 0; nt < 4; nt++) {
                    MMA16816(acc[mt][nt], ahi_f[mt], bhi_f[nt]);
                    MMA16816(acc[mt][nt], ahi_f[mt], blo_f[nt]);
                    MMA16816(acc[mt][nt], alo_f[mt], bhi_f[nt]);
                }
        }
        __syncthreads();
    }

    // epilogue: direct register -> global stores (float2)
    #pragma unroll
    for (int mt = 0; mt < 4; mt++) {
        int gr = brow + wm + mt * 16 + (lane >> 2);
        #pragma unroll
        for (int nt = 0; nt < 4; nt++) {
            int gc = bcol + wn + nt * 8 + (lane & 3) * 2;
            if (gc < Ncols) {
                *(float2*)(C + (size_t)gr * ldc + gc) =
                    make_float2(acc[mt][nt][0], acc[mt][nt][1]);
                *(float2*)(C + (size_t)(gr + 8) * ldc + gc) =
                    make_float2(acc[mt][nt][2], acc[mt][nt][3]);
            }
        }
    }
}

// ---------------- output stage (9 rows) ---------------------------------------
__global__ void build_m4_k(const float* __restrict__ W4, const float* __restrict__ b4,
                           const int* __restrict__ tl, float* __restrict__ M,
                           float* __restrict__ bias) {
    int t = *tl;
    int idx = blockIdx.x * blockDim.x + threadIdx.x;
    if (idx < OUTR * H) {
        int r = idx / H, j = idx % H;
        int c = (r < t) ? r : r + 1;
        M[idx] = W4[(size_t)c * H + j] - W4[(size_t)t * H + j];
    }
    if (idx < OUTR) {
        int c = (idx < t) ? idx : idx + 1;
        bias[idx] = b4[c] - b4[t];
    }
}

__global__ void small_bias_k(const float* __restrict__ A,
                             const float* __restrict__ w, const float* __restrict__ bl,
                             const float* __restrict__ bu, const float* __restrict__ bnext,
                             float* __restrict__ bias) {
    int r = blockIdx.x;
    const float* a = A + (size_t)r * H;
    float au = 0.f, dummy = 0.f;
    for (int j = threadIdx.x; j < H; j += blockDim.x) {
        float v = a[j];
        float p = fmaxf(v, 0.f), n = fminf(v, 0.f);
        au += p * bu[j] + n * bl[j] + v * w[j] * bnext[j];
    }
    blk_reduce2(au, dummy);
    if (threadIdx.x == 0) bias[r] += au;
}

__global__ void zero_k(float* __restrict__ p, int n) {
    int i = blockIdx.x * blockDim.x + threadIdx.x;
    if (i < n) p[i] = 0.f;
}

#define SG_CHUNK 256
__global__ void small_gemm_k(int K, int N, const float* __restrict__ A,
                             const float* __restrict__ ascale,
                             const float* __restrict__ B, float* __restrict__ C) {
    __shared__ float sA[OUTR * SG_CHUNK];
    int k0 = blockIdx.y * SG_CHUNK;
    int n = blockIdx.x * blockDim.x + threadIdx.x;
    for (int idx = threadIdx.x; idx < OUTR * SG_CHUNK; idx += blockDim.x) {
        int r = idx / SG_CHUNK, kk = idx % SG_CHUNK;
        sA[idx] = A[(size_t)r * K + k0 + kk] * ascale[k0 + kk];
    }
    __syncthreads();
    if (n >= N) return;
    float acc[OUTR];
    #pragma unroll
    for (int r = 0; r < OUTR; r++) acc[r] = 0.f;
    #pragma unroll 4
    for (int kk = 0; kk < SG_CHUNK; kk++) {
        float bv = B[(size_t)(k0 + kk) * N + n];
        #pragma unroll
        for (int r = 0; r < OUTR; r++) acc[r] += sA[r * SG_CHUNK + kk] * bv;
    }
    #pragma unroll
    for (int r = 0; r < OUTR; r++) atomicAdd(&C[(size_t)r * N + n], acc[r]);
}

__global__ void final_k(const float* __restrict__ M, const float* __restrict__ lin,
                        const float* __restrict__ uin, const float* __restrict__ bias,
                        float* __restrict__ out) {
    int r = blockIdx.x;
    const float* a = M + (size_t)r * DIN;
    float au = 0.f, dummy = 0.f;
    for (int j = threadIdx.x; j < DIN; j += blockDim.x) {
        float v = a[j];
        au += fmaxf(v, 0.f) * uin[j] + fminf(v, 0.f) * lin[j];
    }
    blk_reduce2(au, dummy);
    if (threadIdx.x == 0) out[r] = au + bias[r];
}

// ---------------- launch ------------------------------------------------------
extern "C" void kernel_launch(void* const* d_in, const int* in_sizes, int n_in,
                              void* d_out, int out_size) {
    const float* W1 = (const float*)d_in[0];
    const float* b1 = (const float*)d_in[1];
    const float* W2 = (const float*)d_in[2];
    const float* b2 = (const float*)d_in[3];
    const float* W3 = (const float*)d_in[4];
    const float* b3 = (const float*)d_in[5];
    const float* W4 = (const float*)d_in[6];
    const float* b4 = (const float*)d_in[7];
    const float* l_in = (const float*)d_in[8];
    const float* u_in = (const float*)d_in[9];
    const float* p_l1 = (const float*)d_in[10];
    const float* p_u1 = (const float*)d_in[11];
    const float* p_l2 = (const float*)d_in[12];
    const float* p_u2 = (const float*)d_in[13];
    const float* p_l3 = (const float*)d_in[14];
    const float* p_u3 = (const float*)d_in[15];
    const int* tl = (const int*)d_in[16];
    float* out = (float*)d_out;

    cudaFuncSetAttribute(gemm_mma_k, cudaFuncAttributeMaxDynamicSharedMemorySize, DSMEM);

    float *T, *A, *lf1, *uf1, *w1, *bl1, *bu1, *lf2, *uf2, *w2, *bl2, *bu2;
    float *lf3, *uf3, *w3, *bl3, *bu3, *cl, *cu, *m4a, *m4b, *bias4;
    __nv_bfloat16 *Ahi, *Alo, *W1th, *W1tl, *W2th, *W2tl;
    cudaGetSymbolAddress((void**)&T, g_T);
    cudaGetSymbolAddress((void**)&A, g_A);
    cudaGetSymbolAddress((void**)&Ahi, g_Ahi);   cudaGetSymbolAddress((void**)&Alo, g_Alo);
    cudaGetSymbolAddress((void**)&W1th, g_W1t_hi); cudaGetSymbolAddress((void**)&W1tl, g_W1t_lo);
    cudaGetSymbolAddress((void**)&W2th, g_W2t_hi); cudaGetSymbolAddress((void**)&W2tl, g_W2t_lo);
    cudaGetSymbolAddress((void**)&lf1, g_lf1); cudaGetSymbolAddress((void**)&uf1, g_uf1);
    cudaGetSymbolAddress((void**)&w1, g_w1);   cudaGetSymbolAddress((void**)&bl1, g_bl1);
    cudaGetSymbolAddress((void**)&bu1, g_bu1);
    cudaGetSymbolAddress((void**)&lf2, g_lf2); cudaGetSymbolAddress((void**)&uf2, g_uf2);
    cudaGetSymbolAddress((void**)&w2, g_w2);   cudaGetSymbolAddress((void**)&bl2, g_bl2);
    cudaGetSymbolAddress((void**)&bu2, g_bu2);
    cudaGetSymbolAddress((void**)&lf3, g_lf3); cudaGetSymbolAddress((void**)&uf3, g_uf3);
    cudaGetSymbolAddress((void**)&w3, g_w3);   cudaGetSymbolAddress((void**)&bl3, g_bl3);
    cudaGetSymbolAddress((void**)&bu3, g_bu3);
    cudaGetSymbolAddress((void**)&cl, g_cl);   cudaGetSymbolAddress((void**)&cu, g_cu);
    cudaGetSymbolAddress((void**)&m4a, g_m4a); cudaGetSymbolAddress((void**)&m4b, g_m4b);
    cudaGetSymbolAddress((void**)&bias4, g_bias4);

    // one-time (per launch) B transpose+split
    transp_conv_k<<<dim3(KTOT / 32, (DIN + 31) / 32), dim3(32, 8)>>>(W1, DIN, W1th, W1tl);
    transp_conv_k<<<dim3(KTOT / 32, H / 32), dim3(32, 8)>>>(W2, H, W2th, W2tl);

    dim3 gmid(NPAD1 / 128, H / 128);         // 7 x 16
    dim3 gbig(H / 128, H / 128);             // 16 x 16

    // ---- stage 1 ----
    concretize_k<<<H, 256>>>(W1, DIN, l_in, u_in, b1, b1, lf1, uf1);
    spu_params_k<<<(H + 255) / 256, 256>>>(lf1, uf1, p_l1, p_u1, w1, bl1, bu1, H);

    // ---- stage 2 ----
    bias2conv_k<<<H, 256>>>(W2, w1, bl1, bu1, b2, b1, cl, cu, Ahi, Alo);
    gemm_mma_k<<<gmid, 256, DSMEM>>>(Ahi, Alo, W1th, W1tl, A, DIN, DIN);
    concretize_k<<<H, 256>>>(A, DIN, l_in, u_in, cl, cu, lf2, uf2);
    spu_params_k<<<(H + 255) / 256, 256>>>(lf2, uf2, p_l2, p_u2, w2, bl2, bu2, H);

    // ---- stage 3 ----
    bias2conv_k<<<H, 256>>>(W3, w2, bl2, bu2, b3, b2, cl, cu, Ahi, Alo);
    gemm_mma_k<<<gbig, 256, DSMEM>>>(Ahi, Alo, W2th, W2tl, T, H, H);
    biasTconv_k<<<H, 256>>>(T, w1, bl1, bu1, b1, cl, cu, Ahi, Alo);
    gemm_mma_k<<<gmid, 256, DSMEM>>>(Ahi, Alo, W1th, W1tl, A, DIN, DIN);
    concretize_k<<<H, 256>>>(A, DIN, l_in, u_in, cl, cu, lf3, uf3);
    spu_params_k<<<(H + 255) / 256, 256>>>(lf3, uf3, p_l3, p_u3, w3, bl3, bu3, H);

    // ---- stage 4: output chain (9 rows) ----
    build_m4_k<<<(OUTR * H + 255) / 256, 256>>>(W4, b4, tl, m4a, bias4);
    small_bias_k<<<OUTR, 256>>>(m4a, w3, bl3, bu3, b3, bias4);
    zero_k<<<(OUTR * H + 255) / 256, 256>>>(m4b, OUTR * H);
    small_gemm_k<<<dim3((H + 127) / 128, H / SG_CHUNK), 128>>>(H, H, m4a, w3, W3, m4b);
    small_bias_k<<<OUTR, 256>>>(m4b, w2, bl2, bu2, b2, bias4);
    zero_k<<<(OUTR * H + 255) / 256, 256>>>(m4a, OUTR * H);
    small_gemm_k<<<dim3((H + 127) / 128, H / SG_CHUNK), 128>>>(H, H, m4b, w2, W2, m4a);
    small_bias_k<<<OUTR, 256>>>(m4a, w1, bl1, bu1, b1, bias4);
    zero_k<<<(OUTR * DIN + 255) / 256, 256>>>(m4b, OUTR * DIN);
    small_gemm_k<<<dim3((DIN + 127) / 128, H / SG_CHUNK), 128>>>(H, DIN, m4a, w1, W1, m4b);
    final_k<<<OUTR, 256>>>(m4b, l_in, u_in, bias4, out);
}

// round 6
// speedup vs baseline: 3.6645x; 1.0038x over previous
#include <cuda_runtime.h>
#include <cuda_bf16.h>
#include <math.h>
#include <stdint.h>

#define H     2048
#define DIN   784
#define OUTR  9
#define KTOT  2048
#define KC    64
#define NCHUNK (KTOT / KC)          // 32
#define TILEB  16384                // 128 rows * 128B (128x64 bf16)
#define DSMEM  (4 * TILEB + 1024)   // single-buffered: Ahi,Alo,Bhi,Blo
#define NPAD1  896                  // DIN padded to 128-multiple

// ---------------- scratch (device globals) ----------------------------------
__device__ float g_T[H * H];        // reused as 2x bf16 [H*H] for stage-3 split
__device__ __nv_bfloat16 g_Ahi[H * H], g_Alo[H * H];
__device__ __nv_bfloat16 g_W1t_hi[NPAD1 * KTOT], g_W1t_lo[NPAD1 * KTOT];  // pad rows stay 0
__device__ __nv_bfloat16 g_W2t_hi[H * KTOT], g_W2t_lo[H * KTOT];
__device__ float g_lf1[H], g_uf1[H], g_w1[H], g_bl1[H], g_bu1[H];
__device__ float g_w2[H], g_bl2[H], g_bu2[H];
__device__ float g_w3[H], g_bl3[H], g_bu3[H];
__device__ float g_cl[H], g_cu[H];
__device__ float g_m4a[OUTR * H], g_m4b[OUTR * H];
__device__ float g_bias4[OUTR];

// ---------------- PTX helpers ------------------------------------------------
__device__ __forceinline__ uint32_t smem_u32(const void* p) {
    uint32_t a;
    asm("{ .reg .u64 t; cvta.to.shared.u64 t, %1; cvt.u32.u64 %0, t; }" : "=r"(a) : "l"(p));
    return a;
}
#define SWZ128(o)  ((o) ^ (((o) >> 3) & 0x70))
#define CP_ASYNC16(dst, gsrc) \
    asm volatile("cp.async.cg.shared.global [%0], [%1], 16;" :: "r"(dst), "l"(gsrc))
#define CP_COMMIT() asm volatile("cp.async.commit_group;" ::: "memory")
#define CP_WAIT0()  asm volatile("cp.async.wait_group 0;" ::: "memory")
#define LDSM_X4(r0, r1, r2, r3, addr) \
    asm volatile("ldmatrix.sync.aligned.m8n8.x4.shared.b16 {%0,%1,%2,%3}, [%4];" \
        : "=r"(r0), "=r"(r1), "=r"(r2), "=r"(r3) : "r"(addr))
#define MMA16816(d, a, b) \
    asm volatile("mma.sync.aligned.m16n8k16.row.col.f32.bf16.bf16.f32 " \
        "{%0,%1,%2,%3}, {%4,%5,%6,%7}, {%8,%9}, {%0,%1,%2,%3};" \
        : "+f"((d)[0]), "+f"((d)[1]), "+f"((d)[2]), "+f"((d)[3]) \
        : "r"((a)[0]), "r"((a)[1]), "r"((a)[2]), "r"((a)[3]), "r"((b)[0]), "r"((b)[1]))

// ---------------- misc helpers ----------------------------------------------
__device__ __forceinline__ float spu_f(float x) {
    if (x >= 0.f) return x * x - 0.5f;
    float s = 1.f / (1.f + expf(x));
    return s - 1.f;
}
__device__ __forceinline__ float dspu_f(float x) {
    if (x >= 0.f) return 2.f * x;
    float s = 1.f / (1.f + expf(x));
    return -s * (1.f - s);
}
__device__ __forceinline__ void blk_reduce2(float &a, float &b) {
    const unsigned m = 0xffffffffu;
    #pragma unroll
    for (int o = 16; o > 0; o >>= 1) {
        a += __shfl_down_sync(m, a, o);
        b += __shfl_down_sync(m, b, o);
    }
    __shared__ float sa[8], sb[8];
    int w = threadIdx.x >> 5, l = threadIdx.x & 31;
    int nw = blockDim.x >> 5;
    if (l == 0) { sa[w] = a; sb[w] = b; }
    __syncthreads();
    if (w == 0) {
        a = (l < nw) ? sa[l] : 0.f;
        b = (l < nw) ? sb[l] : 0.f;
        #pragma unroll
        for (int o = 4; o > 0; o >>= 1) {
            a += __shfl_down_sync(m, a, o);
            b += __shfl_down_sync(m, b, o);
        }
    }
}

// ---------------- elementwise / reduction kernels ---------------------------
__global__ void concretize_k(const float* __restrict__ A, int ncols,
                             const float* __restrict__ lin, const float* __restrict__ uin,
                             const float* __restrict__ cl, const float* __restrict__ cu,
                             float* __restrict__ lf, float* __restrict__ uf) {
    int row = blockIdx.x;
    const float* a = A + (size_t)row * ncols;
    float al = 0.f, au = 0.f;
    for (int j = threadIdx.x; j < ncols; j += blockDim.x) {
        float v = a[j], l = lin[j], u = uin[j];
        float p = fmaxf(v, 0.f), n = fminf(v, 0.f);
        al += p * l + n * u;
        au += p * u + n * l;
    }
    blk_reduce2(al, au);
    if (threadIdx.x == 0) { lf[row] = al + cl[row]; uf[row] = au + cu[row]; }
}

__global__ void spu_params_k(const float* __restrict__ lf, const float* __restrict__ uf,
                             const float* __restrict__ pl, const float* __restrict__ pu,
                             float* __restrict__ w, float* __restrict__ bl,
                             float* __restrict__ bu, int n) {
    int i = blockIdx.x * blockDim.x + threadIdx.x;
    if (i >= n) return;
    float l = lf[i], u = uf[i];
    float k1 = dspu_f(l), k2 = dspu_f(u);
    float klo = fminf(k1, k2), khi = fmaxf(k1, k2);
    float wl = fminf(fmaxf(pl[i], klo), khi);
    float wu = fminf(fmaxf(pu[i], klo), khi);
    float p0 = l, p1 = u, p2 = 0.5f * (l + u), p3 = fminf(fmaxf(0.f, l), u);
    float s0 = spu_f(p0), s1 = spu_f(p1), s2 = spu_f(p2), s3 = spu_f(p3);
    float bl_ = fminf(fminf(s0 - wl * p0, s1 - wl * p1), fminf(s2 - wl * p2, s3 - wl * p3));
    float bu_ = fmaxf(fmaxf(s0 - wu * p0, s1 - wu * p1), fmaxf(s2 - wu * p2, s3 - wu * p3));
    w[i] = wl; bl[i] = bl_; bu[i] = bu_;
}

// bias for (W .* wprev) stage, fused with bf16 hi/lo split of M = W .* wprev
__global__ void bias2conv_k(const float* __restrict__ W,
                            const float* __restrict__ wprev,
                            const float* __restrict__ blprev, const float* __restrict__ buprev,
                            const float* __restrict__ bthis, const float* __restrict__ bprev,
                            float* __restrict__ cl, float* __restrict__ cu,
                            __nv_bfloat16* __restrict__ hi, __nv_bfloat16* __restrict__ lo) {
    int row = blockIdx.x;
    const float* wr = W + (size_t)row * H;
    __nv_bfloat16* hr = hi + (size_t)row * H;
    __nv_bfloat16* lr = lo + (size_t)row * H;
    float al = 0.f, au = 0.f;
    for (int j = threadIdx.x; j < H; j += blockDim.x) {
        float v = wr[j];
        float p = fmaxf(v, 0.f), n = fminf(v, 0.f);
        float m = v * wprev[j];
        al += p * blprev[j] + n * buprev[j] + m * bprev[j];
        au += p * buprev[j] + n * blprev[j] + m * bprev[j];
        __nv_bfloat16 h = __float2bfloat16(m);
        hr[j] = h;
        lr[j] = __float2bfloat16(m - __bfloat162float(h));
    }
    blk_reduce2(al, au);
    if (threadIdx.x == 0) { cl[row] = bthis[row] + al; cu[row] = bthis[row] + au; }
}

// B [K x N] fp32 row-major -> Bt_hi/lo [Npad x K] bf16 (rows >= N stay zero)
__global__ void transp_conv_k(const float* __restrict__ B, int N,
                              __nv_bfloat16* __restrict__ thi, __nv_bfloat16* __restrict__ tlo) {
    __shared__ float t[32][33];
    int k0 = blockIdx.x * 32, n0 = blockIdx.y * 32;
    int x = threadIdx.x, y = threadIdx.y;       // 32 x 8
    for (int yy = y; yy < 32; yy += 8) {
        int n = n0 + x;
        t[yy][x] = (n < N) ? B[(size_t)(k0 + yy) * N + n] : 0.f;
    }
    __syncthreads();
    for (int yy = y; yy < 32; yy += 8) {
        int n = n0 + yy, k = k0 + x;
        if (n < N) {
            float v = t[x][yy];
            __nv_bfloat16 h = __float2bfloat16(v);
            thi[(size_t)n * KTOT + k] = h;
            tlo[(size_t)n * KTOT + k] = __float2bfloat16(v - __bfloat162float(h));
        }
    }
}

// ---------------- mma.sync split-bf16 GEMM with fused epilogues ---------------
// MODE 0 (big):  v=C[gr][gc]; m=v*scale[gc]; store hi/lo bf16 to Ohi/Olo;
//                atomicAdd cl[gr] += pos(v)*blv+neg(v)*buv+m*bvec (cu symmetric)
// MODE 1 (mid):  atomicAdd cl[gr] += pos(v)*lin[gc]+neg(v)*uin[gc] (cu symmetric)
template <int MODE>
__global__ __launch_bounds__(256, 2)
void gemm_mma_k(const __nv_bfloat16* __restrict__ Ahi, const __nv_bfloat16* __restrict__ Alo,
                const __nv_bfloat16* __restrict__ Bhi, const __nv_bfloat16* __restrict__ Blo,
                __nv_bfloat16* __restrict__ Ohi, __nv_bfloat16* __restrict__ Olo,
                const float* __restrict__ scale, const float* __restrict__ bvec,
                const float* __restrict__ blv, const float* __restrict__ buv,
                float* __restrict__ cl, float* __restrict__ cu,
                const float* __restrict__ lin, const float* __restrict__ uin) {
    extern __shared__ char dsm[];
    uint32_t raw = smem_u32(dsm);
    uint32_t dbase = (raw + 1023) & ~1023u;

    int tid = threadIdx.x, wid = tid >> 5, lane = tid & 31;
    int brow = blockIdx.y * 128, bcol = blockIdx.x * 128;
    int wm = (wid >> 2) * 64, wn = (wid & 3) * 32;

    int lrow = tid >> 1, useg = (tid & 1) * 4;
    const __nv_bfloat16* bp[4] = {
        Ahi + (size_t)(brow + lrow) * KTOT, Alo + (size_t)(brow + lrow) * KTOT,
        Bhi + (size_t)(bcol + lrow) * KTOT, Blo + (size_t)(bcol + lrow) * KTOT };
    uint32_t soff[4];
    #pragma unroll
    for (int u = 0; u < 4; u++) soff[u] = SWZ128((uint32_t)(lrow * 128 + (useg + u) * 16));

    float acc[4][4][4];
    #pragma unroll
    for (int mt = 0; mt < 4; mt++)
        #pragma unroll
        for (int nt = 0; nt < 4; nt++)
            #pragma unroll
            for (int q = 0; q < 4; q++) acc[mt][nt][q] = 0.f;

    int l15 = lane & 15, lhi = lane >> 4;
    uint32_t ah_b = dbase + 0 * TILEB, al_b = dbase + 1 * TILEB;
    uint32_t bh_b = dbase + 2 * TILEB, bl_b = dbase + 3 * TILEB;

    for (int chunk = 0; chunk < NCHUNK; chunk++) {
        int k0 = chunk * KC;
        #pragma unroll
        for (int t = 0; t < 4; t++) {
            uint32_t dst = dbase + t * TILEB;
            unsigned long long g =
                (unsigned long long)__cvta_generic_to_global(bp[t] + k0);
            #pragma unroll
            for (int u = 0; u < 4; u++)
                CP_ASYNC16(dst + soff[u], g + (unsigned long long)((useg + u) * 16));
        }
        CP_COMMIT();
        CP_WAIT0();
        __syncthreads();

        #pragma unroll
        for (int kb = 0; kb < 4; kb++) {
            uint32_t kbyte = (uint32_t)(kb * 32 + lhi * 16);
            uint32_t ahi_f[4][4], alo_f[4][4];
            #pragma unroll
            for (int mt = 0; mt < 4; mt++) {
                uint32_t off = SWZ128((uint32_t)((wm + mt * 16 + l15) * 128) + kbyte);
                LDSM_X4(ahi_f[mt][0], ahi_f[mt][1], ahi_f[mt][2], ahi_f[mt][3], ah_b + off);
                LDSM_X4(alo_f[mt][0], alo_f[mt][1], alo_f[mt][2], alo_f[mt][3], al_b + off);
            }
            #pragma unroll
            for (int p = 0; p < 2; p++) {
                uint32_t off = SWZ128((uint32_t)((wn + p * 16 + l15) * 128) + kbyte);
                uint32_t r0, r1, r2, r3;
                uint32_t bhi0[2], bhi1[2], blo0[2], blo1[2];
                LDSM_X4(r0, r1, r2, r3, bh_b + off);
                bhi0[0] = r0; bhi0[1] = r2; bhi1[0] = r1; bhi1[1] = r3;
                LDSM_X4(r0, r1, r2, r3, bl_b + off);
                blo0[0] = r0; blo0[1] = r2; blo1[0] = r1; blo1[1] = r3;
                #pragma unroll
                for (int mt = 0; mt < 4; mt++) {
                    MMA16816(acc[mt][2 * p], ahi_f[mt], bhi0);
                    MMA16816(acc[mt][2 * p], ahi_f[mt], blo0);
                    MMA16816(acc[mt][2 * p], alo_f[mt], bhi0);
                    MMA16816(acc[mt][2 * p + 1], ahi_f[mt], bhi1);
                    MMA16816(acc[mt][2 * p + 1], ahi_f[mt], blo1);
                    MMA16816(acc[mt][2 * p + 1], alo_f[mt], bhi1);
                }
            }
        }
        __syncthreads();
    }

    // ---- fused epilogue ----
    #pragma unroll
    for (int mt = 0; mt < 4; mt++) {
        #pragma unroll
        for (int q = 0; q < 2; q++) {
            int gr = brow + wm + mt * 16 + (lane >> 2) + q * 8;
            float pl = 0.f, pu = 0.f;
            #pragma unroll
            for (int nt = 0; nt < 4; nt++) {
                int gc = bcol + wn + nt * 8 + (lane & 3) * 2;
                float v0 = acc[mt][nt][q * 2 + 0];
                float v1 = acc[mt][nt][q * 2 + 1];
                if (MODE == 0) {
                    float m0 = v0 * scale[gc], m1 = v1 * scale[gc + 1];
                    __nv_bfloat16 h0 = __float2bfloat16(m0);
                    __nv_bfloat16 h1 = __float2bfloat16(m1);
                    __nv_bfloat162 hv; hv.x = h0; hv.y = h1;
                    *(__nv_bfloat162*)(Ohi + (size_t)gr * H + gc) = hv;
                    __nv_bfloat162 lv;
                    lv.x = __float2bfloat16(m0 - __bfloat162float(h0));
                    lv.y = __float2bfloat16(m1 - __bfloat162float(h1));
                    *(__nv_bfloat162*)(Olo + (size_t)gr * H + gc) = lv;
                    float p0 = fmaxf(v0, 0.f), n0 = fminf(v0, 0.f);
                    float p1 = fmaxf(v1, 0.f), n1 = fminf(v1, 0.f);
                    float sb = m0 * bvec[gc] + m1 * bvec[gc + 1];
                    pl += p0 * blv[gc] + n0 * buv[gc] + p1 * blv[gc + 1] + n1 * buv[gc + 1] + sb;
                    pu += p0 * buv[gc] + n0 * blv[gc] + p1 * buv[gc + 1] + n1 * blv[gc + 1] + sb;
                } else {
                    if (gc < DIN) {
                        float l0 = lin[gc], u0 = uin[gc];
                        float l1 = lin[gc + 1], u1 = uin[gc + 1];
                        float p0 = fmaxf(v0, 0.f), n0 = fminf(v0, 0.f);
                        float p1 = fmaxf(v1, 0.f), n1 = fminf(v1, 0.f);
                        pl += p0 * l0 + n0 * u0 + p1 * l1 + n1 * u1;
                        pu += p0 * u0 + n0 * l0 + p1 * u1 + n1 * l1;
                    }
                }
            }
            pl += __shfl_xor_sync(0xffffffffu, pl, 1);
            pl += __shfl_xor_sync(0xffffffffu, pl, 2);
            pu += __shfl_xor_sync(0xffffffffu, pu, 1);
            pu += __shfl_xor_sync(0xffffffffu, pu, 2);
            if ((lane & 3) == 0) {
                atomicAdd(&cl[gr], pl);
                atomicAdd(&cu[gr], pu);
            }
        }
    }
}

// ---------------- output stage (9 rows) ---------------------------------------
__global__ void build_m4_k(const float* __restrict__ W4, const float* __restrict__ b4,
                           const int* __restrict__ tl, float* __restrict__ M,
                           float* __restrict__ bias) {
    int t = *tl;
    int idx = blockIdx.x * blockDim.x + threadIdx.x;
    if (idx < OUTR * H) {
        int r = idx / H, j = idx % H;
        int c = (r < t) ? r : r + 1;
        M[idx] = W4[(size_t)c * H + j] - W4[(size_t)t * H + j];
    }
    if (idx < OUTR) {
        int c = (idx < t) ? idx : idx + 1;
        bias[idx] = b4[c] - b4[t];
    }
}

__global__ void small_bias_k(const float* __restrict__ A,
                             const float* __restrict__ w, const float* __restrict__ bl,
                             const float* __restrict__ bu, const float* __restrict__ bnext,
                             float* __restrict__ bias) {
    int r = blockIdx.x;
    const float* a = A + (size_t)r * H;
    float au = 0.f, dummy = 0.f;
    for (int j = threadIdx.x; j < H; j += blockDim.x) {
        float v = a[j];
        float p = fmaxf(v, 0.f), n = fminf(v, 0.f);
        au += p * bu[j] + n * bl[j] + v * w[j] * bnext[j];
    }
    blk_reduce2(au, dummy);
    if (threadIdx.x == 0) bias[r] += au;
}

__global__ void zero_k(float* __restrict__ p, int n) {
    int i = blockIdx.x * blockDim.x + threadIdx.x;
    if (i < n) p[i] = 0.f;
}

#define SG_CHUNK 256
__global__ void small_gemm_k(int K, int N, const float* __restrict__ A,
                             const float* __restrict__ ascale,
                             const float* __restrict__ B, float* __restrict__ C) {
    __shared__ float sA[OUTR * SG_CHUNK];
    int k0 = blockIdx.y * SG_CHUNK;
    int n = blockIdx.x * blockDim.x + threadIdx.x;
    for (int idx = threadIdx.x; idx < OUTR * SG_CHUNK; idx += blockDim.x) {
        int r = idx / SG_CHUNK, kk = idx % SG_CHUNK;
        sA[idx] = A[(size_t)r * K + k0 + kk] * ascale[k0 + kk];
    }
    __syncthreads();
    if (n >= N) return;
    float acc[OUTR];
    #pragma unroll
    for (int r = 0; r < OUTR; r++) acc[r] = 0.f;
    #pragma unroll 4
    for (int kk = 0; kk < SG_CHUNK; kk++) {
        float bv = B[(size_t)(k0 + kk) * N + n];
        #pragma unroll
        for (int r = 0; r < OUTR; r++) acc[r] += sA[r * SG_CHUNK + kk] * bv;
    }
    #pragma unroll
    for (int r = 0; r < OUTR; r++) atomicAdd(&C[(size_t)r * N + n], acc[r]);
}

__global__ void final_k(const float* __restrict__ M, const float* __restrict__ lin,
                        const float* __restrict__ uin, const float* __restrict__ bias,
                        float* __restrict__ out) {
    int r = blockIdx.x;
    const float* a = M + (size_t)r * DIN;
    float au = 0.f, dummy = 0.f;
    for (int j = threadIdx.x; j < DIN; j += blockDim.x) {
        float v = a[j];
        au += fmaxf(v, 0.f) * uin[j] + fminf(v, 0.f) * lin[j];
    }
    blk_reduce2(au, dummy);
    if (threadIdx.x == 0) out[r] = au + bias[r];
}

// ---------------- launch ------------------------------------------------------
extern "C" void kernel_launch(void* const* d_in, const int* in_sizes, int n_in,
                              void* d_out, int out_size) {
    const float* W1 = (const float*)d_in[0];
    const float* b1 = (const float*)d_in[1];
    const float* W2 = (const float*)d_in[2];
    const float* b2 = (const float*)d_in[3];
    const float* W3 = (const float*)d_in[4];
    const float* b3 = (const float*)d_in[5];
    const float* W4 = (const float*)d_in[6];
    const float* b4 = (const float*)d_in[7];
    const float* l_in = (const float*)d_in[8];
    const float* u_in = (const float*)d_in[9];
    const float* p_l1 = (const float*)d_in[10];
    const float* p_u1 = (const float*)d_in[11];
    const float* p_l2 = (const float*)d_in[12];
    const float* p_u2 = (const float*)d_in[13];
    const float* p_l3 = (const float*)d_in[14];
    const float* p_u3 = (const float*)d_in[15];
    const int* tl = (const int*)d_in[16];
    float* out = (float*)d_out;

    cudaFuncSetAttribute(gemm_mma_k<0>, cudaFuncAttributeMaxDynamicSharedMemorySize, DSMEM);
    cudaFuncSetAttribute(gemm_mma_k<1>, cudaFuncAttributeMaxDynamicSharedMemorySize, DSMEM);

    float *T, *lf1, *uf1, *w1, *bl1, *bu1, *w2, *bl2, *bu2;
    float *w3, *bl3, *bu3, *cl, *cu, *m4a, *m4b, *bias4;
    __nv_bfloat16 *Ahi, *Alo, *W1th, *W1tl, *W2th, *W2tl;
    cudaGetSymbolAddress((void**)&T, g_T);
    cudaGetSymbolAddress((void**)&Ahi, g_Ahi);   cudaGetSymbolAddress((void**)&Alo, g_Alo);
    cudaGetSymbolAddress((void**)&W1th, g_W1t_hi); cudaGetSymbolAddress((void**)&W1tl, g_W1t_lo);
    cudaGetSymbolAddress((void**)&W2th, g_W2t_hi); cudaGetSymbolAddress((void**)&W2tl, g_W2t_lo);
    cudaGetSymbolAddress((void**)&lf1, g_lf1); cudaGetSymbolAddress((void**)&uf1, g_uf1);
    cudaGetSymbolAddress((void**)&w1, g_w1);   cudaGetSymbolAddress((void**)&bl1, g_bl1);
    cudaGetSymbolAddress((void**)&bu1, g_bu1);
    cudaGetSymbolAddress((void**)&w2, g_w2);   cudaGetSymbolAddress((void**)&bl2, g_bl2);
    cudaGetSymbolAddress((void**)&bu2, g_bu2);
    cudaGetSymbolAddress((void**)&w3, g_w3);   cudaGetSymbolAddress((void**)&bl3, g_bl3);
    cudaGetSymbolAddress((void**)&bu3, g_bu3);
    cudaGetSymbolAddress((void**)&cl, g_cl);   cudaGetSymbolAddress((void**)&cu, g_cu);
    cudaGetSymbolAddress((void**)&m4a, g_m4a); cudaGetSymbolAddress((void**)&m4b, g_m4b);
    cudaGetSymbolAddress((void**)&bias4, g_bias4);

    // stage-3 split output aliases g_T (16MB fp32 = 2 x 8MB bf16)
    __nv_bfloat16* Thi = (__nv_bfloat16*)T;
    __nv_bfloat16* Tlo = ((__nv_bfloat16*)T) + (size_t)H * H;

    // one-time (per launch) B transpose+split
    transp_conv_k<<<dim3(KTOT / 32, (DIN + 31) / 32), dim3(32, 8)>>>(W1, DIN, W1th, W1tl);
    transp_conv_k<<<dim3(KTOT / 32, H / 32), dim3(32, 8)>>>(W2, H, W2th, W2tl);

    dim3 gmid(NPAD1 / 128, H / 128);         // 7 x 16
    dim3 gbig(H / 128, H / 128);             // 16 x 16

    // ---- stage 1 ----
    concretize_k<<<H, 256>>>(W1, DIN, l_in, u_in, b1, b1, lf1, uf1);
    spu_params_k<<<(H + 63) / 64, 64>>>(lf1, uf1, p_l1, p_u1, w1, bl1, bu1, H);

    // ---- stage 2 ----
    bias2conv_k<<<H, 256>>>(W2, w1, bl1, bu1, b2, b1, cl, cu, Ahi, Alo);
    gemm_mma_k<1><<<gmid, 256, DSMEM>>>(Ahi, Alo, W1th, W1tl, nullptr, nullptr,
                                        nullptr, nullptr, nullptr, nullptr,
                                        cl, cu, l_in, u_in);
    spu_params_k<<<(H + 63) / 64, 64>>>(cl, cu, p_l2, p_u2, w2, bl2, bu2, H);

    // ---- stage 3 ----
    bias2conv_k<<<H, 256>>>(W3, w2, bl2, bu2, b3, b2, cl, cu, Ahi, Alo);
    gemm_mma_k<0><<<gbig, 256, DSMEM>>>(Ahi, Alo, W2th, W2tl, Thi, Tlo,
                                        w1, b1, bl1, bu1, cl, cu, nullptr, nullptr);
    gemm_mma_k<1><<<gmid, 256, DSMEM>>>(Thi, Tlo, W1th, W1tl, nullptr, nullptr,
                                        nullptr, nullptr, nullptr, nullptr,
                                        cl, cu, l_in, u_in);
    spu_params_k<<<(H + 63) / 64, 64>>>(cl, cu, p_l3, p_u3, w3, bl3, bu3, H);

    // ---- stage 4: output chain (9 rows) ----
    build_m4_k<<<(OUTR * H + 255) / 256, 256>>>(W4, b4, tl, m4a, bias4);
    small_bias_k<<<OUTR, 256>>>(m4a, w3, bl3, bu3, b3, bias4);
    zero_k<<<(OUTR * H + 255) / 256, 256>>>(m4b, OUTR * H);
    small_gemm_k<<<dim3((H + 127) / 128, H / SG_CHUNK), 128>>>(H, H, m4a, w3, W3, m4b);
    small_bias_k<<<OUTR, 256>>>(m4b, w2, bl2, bu2, b2, bias4);
    zero_k<<<(OUTR * H + 255) / 256, 256>>>(m4a, OUTR * H);
    small_gemm_k<<<dim3((H + 127) / 128, H / SG_CHUNK), 128>>>(H, H, m4b, w2, W2, m4a);
    small_bias_k<<<OUTR, 256>>>(m4a, w1, bl1, bu1, b1, bias4);
    zero_k<<<(OUTR * DIN + 255) / 256, 256>>>(m4b, OUTR * DIN);
    small_gemm_k<<<dim3((DIN + 127) / 128, H / SG_CHUNK), 128>>>(H, DIN, m4a, w1, W1, m4b);
    final_k<<<OUTR, 256>>>(m4b, l_in, u_in, bias4, out);
}

// round 7
// speedup vs baseline: 4.1925x; 1.1441x over previous
#include <cuda_runtime.h>
#include <cuda_bf16.h>
#include <math.h>
#include <stdint.h>

#define H     2048
#define DIN   784
#define OUTR  9
#define KTOT  2048
#define KC    32
#define NCHUNK (KTOT / KC)          // 64
#define TILEB  8192                 // 128 rows * 64B (128x32 bf16)
#define STAGEB (4 * TILEB)          // 32KB: Ahi,Alo,Bhi,Blo
#define NSTAGE 3
#define DSMEM  (NSTAGE * STAGEB + 1024)
#define NPAD1  896                  // DIN padded to 128-multiple

// ---------------- scratch (device globals) ----------------------------------
__device__ float g_T[H * H];        // reused as 2x bf16 [H*H] for stage-3 split
__device__ __nv_bfloat16 g_Ahi[H * H], g_Alo[H * H];
__device__ __nv_bfloat16 g_W1t_hi[NPAD1 * KTOT], g_W1t_lo[NPAD1 * KTOT];  // pad rows stay 0
__device__ __nv_bfloat16 g_W2t_hi[H * KTOT], g_W2t_lo[H * KTOT];
__device__ float g_lf1[H], g_uf1[H], g_w1[H], g_bl1[H], g_bu1[H];
__device__ float g_w2[H], g_bl2[H], g_bu2[H];
__device__ float g_w3[H], g_bl3[H], g_bu3[H];
__device__ float g_cl[H], g_cu[H];
__device__ float g_m4a[OUTR * H], g_m4b[OUTR * H];
__device__ float g_bias4[OUTR];

// ---------------- PTX helpers ------------------------------------------------
__device__ __forceinline__ uint32_t smem_u32(const void* p) {
    uint32_t a;
    asm("{ .reg .u64 t; cvta.to.shared.u64 t, %1; cvt.u32.u64 %0, t; }" : "=r"(a) : "l"(p));
    return a;
}
#define SWZ64(o)   ((o) ^ (((o) >> 3) & 0x30))
#define CP_ASYNC16(dst, gsrc) \
    asm volatile("cp.async.cg.shared.global [%0], [%1], 16;" :: "r"(dst), "l"(gsrc))
#define CP_COMMIT() asm volatile("cp.async.commit_group;" ::: "memory")
#define CP_WAIT(n)  asm volatile("cp.async.wait_group %0;" :: "n"(n) : "memory")
#define LDSM_X4(r0, r1, r2, r3, addr) \
    asm volatile("ldmatrix.sync.aligned.m8n8.x4.shared.b16 {%0,%1,%2,%3}, [%4];" \
        : "=r"(r0), "=r"(r1), "=r"(r2), "=r"(r3) : "r"(addr))
#define MMA16816(d, a, b) \
    asm volatile("mma.sync.aligned.m16n8k16.row.col.f32.bf16.bf16.f32 " \
        "{%0,%1,%2,%3}, {%4,%5,%6,%7}, {%8,%9}, {%0,%1,%2,%3};" \
        : "+f"((d)[0]), "+f"((d)[1]), "+f"((d)[2]), "+f"((d)[3]) \
        : "r"((a)[0]), "r"((a)[1]), "r"((a)[2]), "r"((a)[3]), "r"((b)[0]), "r"((b)[1]))

// ---------------- misc helpers ----------------------------------------------
__device__ __forceinline__ float spu_f(float x) {
    if (x >= 0.f) return x * x - 0.5f;
    float s = 1.f / (1.f + expf(x));
    return s - 1.f;
}
__device__ __forceinline__ float dspu_f(float x) {
    if (x >= 0.f) return 2.f * x;
    float s = 1.f / (1.f + expf(x));
    return -s * (1.f - s);
}
__device__ __forceinline__ void blk_reduce2(float &a, float &b) {
    const unsigned m = 0xffffffffu;
    #pragma unroll
    for (int o = 16; o > 0; o >>= 1) {
        a += __shfl_down_sync(m, a, o);
        b += __shfl_down_sync(m, b, o);
    }
    __shared__ float sa[8], sb[8];
    int w = threadIdx.x >> 5, l = threadIdx.x & 31;
    int nw = blockDim.x >> 5;
    if (l == 0) { sa[w] = a; sb[w] = b; }
    __syncthreads();
    if (w == 0) {
        a = (l < nw) ? sa[l] : 0.f;
        b = (l < nw) ? sb[l] : 0.f;
        #pragma unroll
        for (int o = 4; o > 0; o >>= 1) {
            a += __shfl_down_sync(m, a, o);
            b += __shfl_down_sync(m, b, o);
        }
    }
}

// ---------------- elementwise / reduction kernels ---------------------------
__global__ void concretize_k(const float* __restrict__ A, int ncols,
                             const float* __restrict__ lin, const float* __restrict__ uin,
                             const float* __restrict__ cl, const float* __restrict__ cu,
                             float* __restrict__ lf, float* __restrict__ uf) {
    int row = blockIdx.x;
    const float* a = A + (size_t)row * ncols;
    float al = 0.f, au = 0.f;
    for (int j = threadIdx.x; j < ncols; j += blockDim.x) {
        float v = a[j], l = lin[j], u = uin[j];
        float p = fmaxf(v, 0.f), n = fminf(v, 0.f);
        al += p * l + n * u;
        au += p * u + n * l;
    }
    blk_reduce2(al, au);
    if (threadIdx.x == 0) { lf[row] = al + cl[row]; uf[row] = au + cu[row]; }
}

__global__ void spu_params_k(const float* __restrict__ lf, const float* __restrict__ uf,
                             const float* __restrict__ pl, const float* __restrict__ pu,
                             float* __restrict__ w, float* __restrict__ bl,
                             float* __restrict__ bu, int n) {
    int i = blockIdx.x * blockDim.x + threadIdx.x;
    if (i >= n) return;
    float l = lf[i], u = uf[i];
    float k1 = dspu_f(l), k2 = dspu_f(u);
    float klo = fminf(k1, k2), khi = fmaxf(k1, k2);
    float wl = fminf(fmaxf(pl[i], klo), khi);
    float wu = fminf(fmaxf(pu[i], klo), khi);
    float p0 = l, p1 = u, p2 = 0.5f * (l + u), p3 = fminf(fmaxf(0.f, l), u);
    float s0 = spu_f(p0), s1 = spu_f(p1), s2 = spu_f(p2), s3 = spu_f(p3);
    float bl_ = fminf(fminf(s0 - wl * p0, s1 - wl * p1), fminf(s2 - wl * p2, s3 - wl * p3));
    float bu_ = fmaxf(fmaxf(s0 - wu * p0, s1 - wu * p1), fmaxf(s2 - wu * p2, s3 - wu * p3));
    w[i] = wl; bl[i] = bl_; bu[i] = bu_;
}

// bias for (W .* wprev) stage, fused with bf16 hi/lo split of M = W .* wprev
__global__ void bias2conv_k(const float* __restrict__ W,
                            const float* __restrict__ wprev,
                            const float* __restrict__ blprev, const float* __restrict__ buprev,
                            const float* __restrict__ bthis, const float* __restrict__ bprev,
                            float* __restrict__ cl, float* __restrict__ cu,
                            __nv_bfloat16* __restrict__ hi, __nv_bfloat16* __restrict__ lo) {
    int row = blockIdx.x;
    const float* wr = W + (size_t)row * H;
    __nv_bfloat16* hr = hi + (size_t)row * H;
    __nv_bfloat16* lr = lo + (size_t)row * H;
    float al = 0.f, au = 0.f;
    for (int j = threadIdx.x; j < H; j += blockDim.x) {
        float v = wr[j];
        float p = fmaxf(v, 0.f), n = fminf(v, 0.f);
        float m = v * wprev[j];
        al += p * blprev[j] + n * buprev[j] + m * bprev[j];
        au += p * buprev[j] + n * blprev[j] + m * bprev[j];
        __nv_bfloat16 h = __float2bfloat16(m);
        hr[j] = h;
        lr[j] = __float2bfloat16(m - __bfloat162float(h));
    }
    blk_reduce2(al, au);
    if (threadIdx.x == 0) { cl[row] = bthis[row] + al; cu[row] = bthis[row] + au; }
}

// B [K x N] fp32 row-major -> Bt_hi/lo [Npad x K] bf16 (rows >= N stay zero)
__global__ void transp_conv_k(const float* __restrict__ B, int N,
                              __nv_bfloat16* __restrict__ thi, __nv_bfloat16* __restrict__ tlo) {
    __shared__ float t[32][33];
    int k0 = blockIdx.x * 32, n0 = blockIdx.y * 32;
    int x = threadIdx.x, y = threadIdx.y;       // 32 x 8
    for (int yy = y; yy < 32; yy += 8) {
        int n = n0 + x;
        t[yy][x] = (n < N) ? B[(size_t)(k0 + yy) * N + n] : 0.f;
    }
    __syncthreads();
    for (int yy = y; yy < 32; yy += 8) {
        int n = n0 + yy, k = k0 + x;
        if (n < N) {
            float v = t[x][yy];
            __nv_bfloat16 h = __float2bfloat16(v);
            thi[(size_t)n * KTOT + k] = h;
            tlo[(size_t)n * KTOT + k] = __float2bfloat16(v - __bfloat162float(h));
        }
    }
}

// ---------------- mma.sync split-bf16 GEMM, 3-stage cp.async pipeline --------
// MODE 0 (big):  v=C[gr][gc]; m=v*scale[gc]; store hi/lo bf16 to Ohi/Olo;
//                atomicAdd cl[gr] += pos(v)*blv+neg(v)*buv+m*bvec (cu symmetric)
// MODE 1 (mid):  atomicAdd cl[gr] += pos(v)*lin[gc]+neg(v)*uin[gc] (cu symmetric)
template <int MODE>
__global__ __launch_bounds__(256, 2)
void gemm_mma_k(const __nv_bfloat16* __restrict__ Ahi, const __nv_bfloat16* __restrict__ Alo,
                const __nv_bfloat16* __restrict__ Bhi, const __nv_bfloat16* __restrict__ Blo,
                __nv_bfloat16* __restrict__ Ohi, __nv_bfloat16* __restrict__ Olo,
                const float* __restrict__ scale, const float* __restrict__ bvec,
                const float* __restrict__ blv, const float* __restrict__ buv,
                float* __restrict__ cl, float* __restrict__ cu,
                const float* __restrict__ lin, const float* __restrict__ uin) {
    extern __shared__ char dsm[];
    uint32_t raw = smem_u32(dsm);
    uint32_t dbase = (raw + 1023) & ~1023u;

    int tid = threadIdx.x, wid = tid >> 5, lane = tid & 31;
    int brow = blockIdx.y * 128, bcol = blockIdx.x * 128;
    int wm = (wid >> 2) * 64, wn = (wid & 3) * 32;

    // ---- staging map: 2048 x 16B segs per chunk, 8 per thread ----
    const __nv_bfloat16* gbase[4] = {
        Ahi + (size_t)brow * KTOT, Alo + (size_t)brow * KTOT,
        Bhi + (size_t)bcol * KTOT, Blo + (size_t)bcol * KTOT };
    const __nv_bfloat16* gsrc[8];
    uint32_t sdst[8];
    #pragma unroll
    for (int i = 0; i < 8; i++) {
        int s = i * 256 + tid;
        int t = s >> 9, row = (s >> 2) & 127, sg = s & 3;
        gsrc[i] = gbase[t] + (size_t)row * KTOT + sg * 8;
        sdst[i] = (uint32_t)(t * TILEB) + SWZ64((uint32_t)(row * 64 + sg * 16));
    }

    float acc[4][4][4];
    #pragma unroll
    for (int mt = 0; mt < 4; mt++)
        #pragma unroll
        for (int nt = 0; nt < 4; nt++)
            #pragma unroll
            for (int q = 0; q < 4; q++) acc[mt][nt][q] = 0.f;

    int l15 = lane & 15, lhi = lane >> 4;

    // prologue: stages 0,1
    #pragma unroll
    for (int st = 0; st < 2; st++) {
        uint32_t sb = dbase + st * STAGEB;
        int k0 = st * KC;
        #pragma unroll
        for (int i = 0; i < 8; i++) CP_ASYNC16(sb + sdst[i], gsrc[i] + k0);
        CP_COMMIT();
    }

    int stage = 0;
    for (int chunk = 0; chunk < NCHUNK; chunk++) {
        if (chunk + 2 < NCHUNK) {
            int ns = stage + 2; if (ns >= NSTAGE) ns -= NSTAGE;
            uint32_t sb = dbase + ns * STAGEB;
            int k0 = (chunk + 2) * KC;
            #pragma unroll
            for (int i = 0; i < 8; i++) CP_ASYNC16(sb + sdst[i], gsrc[i] + k0);
            CP_COMMIT();
            CP_WAIT(2);
        } else if (chunk + 1 < NCHUNK) {
            CP_WAIT(1);
        } else {
            CP_WAIT(0);
        }
        __syncthreads();

        uint32_t ah_b = dbase + stage * STAGEB;
        uint32_t al_b = ah_b + TILEB, bh_b = ah_b + 2 * TILEB, bl_b = ah_b + 3 * TILEB;

        #pragma unroll
        for (int kb = 0; kb < 2; kb++) {
            uint32_t kbyte = (uint32_t)(kb * 32 + lhi * 16);
            uint32_t ahi_f[4][4], alo_f[4][4];
            #pragma unroll
            for (int mt = 0; mt < 4; mt++) {
                uint32_t off = SWZ64((uint32_t)((wm + mt * 16 + l15) * 64) + kbyte);
                LDSM_X4(ahi_f[mt][0], ahi_f[mt][1], ahi_f[mt][2], ahi_f[mt][3], ah_b + off);
                LDSM_X4(alo_f[mt][0], alo_f[mt][1], alo_f[mt][2], alo_f[mt][3], al_b + off);
            }
            #pragma unroll
            for (int p = 0; p < 2; p++) {
                uint32_t off = SWZ64((uint32_t)((wn + p * 16 + l15) * 64) + kbyte);
                uint32_t r0, r1, r2, r3;
                uint32_t bhi0[2], bhi1[2], blo0[2], blo1[2];
                LDSM_X4(r0, r1, r2, r3, bh_b + off);
                bhi0[0] = r0; bhi0[1] = r2; bhi1[0] = r1; bhi1[1] = r3;
                LDSM_X4(r0, r1, r2, r3, bl_b + off);
                blo0[0] = r0; blo0[1] = r2; blo1[0] = r1; blo1[1] = r3;
                #pragma unroll
                for (int mt = 0; mt < 4; mt++) {
                    MMA16816(acc[mt][2 * p], ahi_f[mt], bhi0);
                    MMA16816(acc[mt][2 * p], ahi_f[mt], blo0);
                    MMA16816(acc[mt][2 * p], alo_f[mt], bhi0);
                    MMA16816(acc[mt][2 * p + 1], ahi_f[mt], bhi1);
                    MMA16816(acc[mt][2 * p + 1], ahi_f[mt], blo1);
                    MMA16816(acc[mt][2 * p + 1], alo_f[mt], bhi1);
                }
            }
        }
        __syncthreads();
        stage++; if (stage >= NSTAGE) stage -= NSTAGE;
    }

    // ---- fused epilogue ----
    #pragma unroll
    for (int mt = 0; mt < 4; mt++) {
        #pragma unroll
        for (int q = 0; q < 2; q++) {
            int gr = brow + wm + mt * 16 + (lane >> 2) + q * 8;
            float pl = 0.f, pu = 0.f;
            #pragma unroll
            for (int nt = 0; nt < 4; nt++) {
                int gc = bcol + wn + nt * 8 + (lane & 3) * 2;
                float v0 = acc[mt][nt][q * 2 + 0];
                float v1 = acc[mt][nt][q * 2 + 1];
                if (MODE == 0) {
                    float m0 = v0 * scale[gc], m1 = v1 * scale[gc + 1];
                    __nv_bfloat16 h0 = __float2bfloat16(m0);
                    __nv_bfloat16 h1 = __float2bfloat16(m1);
                    __nv_bfloat162 hv; hv.x = h0; hv.y = h1;
                    *(__nv_bfloat162*)(Ohi + (size_t)gr * H + gc) = hv;
                    __nv_bfloat162 lv;
                    lv.x = __float2bfloat16(m0 - __bfloat162float(h0));
                    lv.y = __float2bfloat16(m1 - __bfloat162float(h1));
                    *(__nv_bfloat162*)(Olo + (size_t)gr * H + gc) = lv;
                    float p0 = fmaxf(v0, 0.f), n0 = fminf(v0, 0.f);
                    float p1 = fmaxf(v1, 0.f), n1 = fminf(v1, 0.f);
                    float sb = m0 * bvec[gc] + m1 * bvec[gc + 1];
                    pl += p0 * blv[gc] + n0 * buv[gc] + p1 * blv[gc + 1] + n1 * buv[gc + 1] + sb;
                    pu += p0 * buv[gc] + n0 * blv[gc] + p1 * buv[gc + 1] + n1 * blv[gc + 1] + sb;
                } else {
                    if (gc < DIN) {
                        float l0 = lin[gc], u0 = uin[gc];
                        float l1 = lin[gc + 1], u1 = uin[gc + 1];
                        float p0 = fmaxf(v0, 0.f), n0 = fminf(v0, 0.f);
                        float p1 = fmaxf(v1, 0.f), n1 = fminf(v1, 0.f);
                        pl += p0 * l0 + n0 * u0 + p1 * l1 + n1 * u1;
                        pu += p0 * u0 + n0 * l0 + p1 * u1 + n1 * l1;
                    }
                }
            }
            pl += __shfl_xor_sync(0xffffffffu, pl, 1);
            pl += __shfl_xor_sync(0xffffffffu, pl, 2);
            pu += __shfl_xor_sync(0xffffffffu, pu, 1);
            pu += __shfl_xor_sync(0xffffffffu, pu, 2);
            if ((lane & 3) == 0) {
                atomicAdd(&cl[gr], pl);
                atomicAdd(&cu[gr], pu);
            }
        }
    }
}

// ---------------- output stage (9 rows) ---------------------------------------
__global__ void build_m4_k(const float* __restrict__ W4, const float* __restrict__ b4,
                           const int* __restrict__ tl, float* __restrict__ M,
                           float* __restrict__ bias) {
    int t = *tl;
    int idx = blockIdx.x * blockDim.x + threadIdx.x;
    if (idx < OUTR * H) {
        int r = idx / H, j = idx % H;
        int c = (r < t) ? r : r + 1;
        M[idx] = W4[(size_t)c * H + j] - W4[(size_t)t * H + j];
    }
    if (idx < OUTR) {
        int c = (idx < t) ? idx : idx + 1;
        bias[idx] = b4[c] - b4[t];
    }
}

__global__ void small_bias_k(const float* __restrict__ A,
                             const float* __restrict__ w, const float* __restrict__ bl,
                             const float* __restrict__ bu, const float* __restrict__ bnext,
                             float* __restrict__ bias) {
    int r = blockIdx.x;
    const float* a = A + (size_t)r * H;
    float au = 0.f, dummy = 0.f;
    for (int j = threadIdx.x; j < H; j += blockDim.x) {
        float v = a[j];
        float p = fmaxf(v, 0.f), n = fminf(v, 0.f);
        au += p * bu[j] + n * bl[j] + v * w[j] * bnext[j];
    }
    blk_reduce2(au, dummy);
    if (threadIdx.x == 0) bias[r] += au;
}

__global__ void zero_k(float* __restrict__ p, int n) {
    int i = blockIdx.x * blockDim.x + threadIdx.x;
    if (i < n) p[i] = 0.f;
}

#define SG_CHUNK 256
__global__ void small_gemm_k(int K, int N, const float* __restrict__ A,
                             const float* __restrict__ ascale,
                             const float* __restrict__ B, float* __restrict__ C) {
    __shared__ float sA[OUTR * SG_CHUNK];
    int k0 = blockIdx.y * SG_CHUNK;
    int n = blockIdx.x * blockDim.x + threadIdx.x;
    for (int idx = threadIdx.x; idx < OUTR * SG_CHUNK; idx += blockDim.x) {
        int r = idx / SG_CHUNK, kk = idx % SG_CHUNK;
        sA[idx] = A[(size_t)r * K + k0 + kk] * ascale[k0 + kk];
    }
    __syncthreads();
    if (n >= N) return;
    float acc[OUTR];
    #pragma unroll
    for (int r = 0; r < OUTR; r++) acc[r] = 0.f;
    #pragma unroll 4
    for (int kk = 0; kk < SG_CHUNK; kk++) {
        float bv = B[(size_t)(k0 + kk) * N + n];
        #pragma unroll
        for (int r = 0; r < OUTR; r++) acc[r] += sA[r * SG_CHUNK + kk] * bv;
    }
    #pragma unroll
    for (int r = 0; r < OUTR; r++) atomicAdd(&C[(size_t)r * N + n], acc[r]);
}

__global__ void final_k(const float* __restrict__ M, const float* __restrict__ lin,
                        const float* __restrict__ uin, const float* __restrict__ bias,
                        float* __restrict__ out) {
    int r = blockIdx.x;
    const float* a = M + (size_t)r * DIN;
    float au = 0.f, dummy = 0.f;
    for (int j = threadIdx.x; j < DIN; j += blockDim.x) {
        float v = a[j];
        au += fmaxf(v, 0.f) * uin[j] + fminf(v, 0.f) * lin[j];
    }
    blk_reduce2(au, dummy);
    if (threadIdx.x == 0) out[r] = au + bias[r];
}

// ---------------- launch ------------------------------------------------------
extern "C" void kernel_launch(void* const* d_in, const int* in_sizes, int n_in,
                              void* d_out, int out_size) {
    const float* W1 = (const float*)d_in[0];
    const float* b1 = (const float*)d_in[1];
    const float* W2 = (const float*)d_in[2];
    const float* b2 = (const float*)d_in[3];
    const float* W3 = (const float*)d_in[4];
    const float* b3 = (const float*)d_in[5];
    const float* W4 = (const float*)d_in[6];
    const float* b4 = (const float*)d_in[7];
    const float* l_in = (const float*)d_in[8];
    const float* u_in = (const float*)d_in[9];
    const float* p_l1 = (const float*)d_in[10];
    const float* p_u1 = (const float*)d_in[11];
    const float* p_l2 = (const float*)d_in[12];
    const float* p_u2 = (const float*)d_in[13];
    const float* p_l3 = (const float*)d_in[14];
    const float* p_u3 = (const float*)d_in[15];
    const int* tl = (const int*)d_in[16];
    float* out = (float*)d_out;

    cudaFuncSetAttribute(gemm_mma_k<0>, cudaFuncAttributeMaxDynamicSharedMemorySize, DSMEM);
    cudaFuncSetAttribute(gemm_mma_k<1>, cudaFuncAttributeMaxDynamicSharedMemorySize, DSMEM);

    float *T, *lf1, *uf1, *w1, *bl1, *bu1, *w2, *bl2, *bu2;
    float *w3, *bl3, *bu3, *cl, *cu, *m4a, *m4b, *bias4;
    __nv_bfloat16 *Ahi, *Alo, *W1th, *W1tl, *W2th, *W2tl;
    cudaGetSymbolAddress((void**)&T, g_T);
    cudaGetSymbolAddress((void**)&Ahi, g_Ahi);   cudaGetSymbolAddress((void**)&Alo, g_Alo);
    cudaGetSymbolAddress((void**)&W1th, g_W1t_hi); cudaGetSymbolAddress((void**)&W1tl, g_W1t_lo);
    cudaGetSymbolAddress((void**)&W2th, g_W2t_hi); cudaGetSymbolAddress((void**)&W2tl, g_W2t_lo);
    cudaGetSymbolAddress((void**)&lf1, g_lf1); cudaGetSymbolAddress((void**)&uf1, g_uf1);
    cudaGetSymbolAddress((void**)&w1, g_w1);   cudaGetSymbolAddress((void**)&bl1, g_bl1);
    cudaGetSymbolAddress((void**)&bu1, g_bu1);
    cudaGetSymbolAddress((void**)&w2, g_w2);   cudaGetSymbolAddress((void**)&bl2, g_bl2);
    cudaGetSymbolAddress((void**)&bu2, g_bu2);
    cudaGetSymbolAddress((void**)&w3, g_w3);   cudaGetSymbolAddress((void**)&bl3, g_bl3);
    cudaGetSymbolAddress((void**)&bu3, g_bu3);
    cudaGetSymbolAddress((void**)&cl, g_cl);   cudaGetSymbolAddress((void**)&cu, g_cu);
    cudaGetSymbolAddress((void**)&m4a, g_m4a); cudaGetSymbolAddress((void**)&m4b, g_m4b);
    cudaGetSymbolAddress((void**)&bias4, g_bias4);

    // stage-3 split output aliases g_T (16MB fp32 = 2 x 8MB bf16)
    __nv_bfloat16* Thi = (__nv_bfloat16*)T;
    __nv_bfloat16* Tlo = ((__nv_bfloat16*)T) + (size_t)H * H;

    // one-time (per launch) B transpose+split
    transp_conv_k<<<dim3(KTOT / 32, (DIN + 31) / 32), dim3(32, 8)>>>(W1, DIN, W1th, W1tl);
    transp_conv_k<<<dim3(KTOT / 32, H / 32), dim3(32, 8)>>>(W2, H, W2th, W2tl);

    dim3 gmid(NPAD1 / 128, H / 128);         // 7 x 16
    dim3 gbig(H / 128, H / 128);             // 16 x 16

    // ---- stage 1 ----
    concretize_k<<<H, 256>>>(W1, DIN, l_in, u_in, b1, b1, lf1, uf1);
    spu_params_k<<<(H + 63) / 64, 64>>>(lf1, uf1, p_l1, p_u1, w1, bl1, bu1, H);

    // ---- stage 2 ----
    bias2conv_k<<<H, 256>>>(W2, w1, bl1, bu1, b2, b1, cl, cu, Ahi, Alo);
    gemm_mma_k<1><<<gmid, 256, DSMEM>>>(Ahi, Alo, W1th, W1tl, nullptr, nullptr,
                                        nullptr, nullptr, nullptr, nullptr,
                                        cl, cu, l_in, u_in);
    spu_params_k<<<(H + 63) / 64, 64>>>(cl, cu, p_l2, p_u2, w2, bl2, bu2, H);

    // ---- stage 3 ----
    bias2conv_k<<<H, 256>>>(W3, w2, bl2, bu2, b3, b2, cl, cu, Ahi, Alo);
    gemm_mma_k<0><<<gbig, 256, DSMEM>>>(Ahi, Alo, W2th, W2tl, Thi, Tlo,
                                        w1, b1, bl1, bu1, cl, cu, nullptr, nullptr);
    gemm_mma_k<1><<<gmid, 256, DSMEM>>>(Thi, Tlo, W1th, W1tl, nullptr, nullptr,
                                        nullptr, nullptr, nullptr, nullptr,
                                        cl, cu, l_in, u_in);
    spu_params_k<<<(H + 63) / 64, 64>>>(cl, cu, p_l3, p_u3, w3, bl3, bu3, H);

    // ---- stage 4: output chain (9 rows) ----
    build_m4_k<<<(OUTR * H + 255) / 256, 256>>>(W4, b4, tl, m4a, bias4);
    small_bias_k<<<OUTR, 256>>>(m4a, w3, bl3, bu3, b3, bias4);
    zero_k<<<(OUTR * H + 255) / 256, 256>>>(m4b, OUTR * H);
    small_gemm_k<<<dim3((H + 127) / 128, H / SG_CHUNK), 128>>>(H, H, m4a, w3, W3, m4b);
    small_bias_k<<<OUTR, 256>>>(m4b, w2, bl2, bu2, b2, bias4);
    zero_k<<<(OUTR * H + 255) / 256, 256>>>(m4a, OUTR * H);
    small_gemm_k<<<dim3((H + 127) / 128, H / SG_CHUNK), 128>>>(H, H, m4b, w2, W2, m4a);
    small_bias_k<<<OUTR, 256>>>(m4a, w1, bl1, bu1, b1, bias4);
    zero_k<<<(OUTR * DIN + 255) / 256, 256>>>(m4b, OUTR * DIN);
    small_gemm_k<<<dim3((DIN + 127) / 128, H / SG_CHUNK), 128>>>(H, DIN, m4a, w1, W1, m4b);
    final_k<<<OUTR, 256>>>(m4b, l_in, u_in, bias4, out);
}